// round 14
// baseline (speedup 1.0000x reference)
#include <cuda_runtime.h>
#include <cuda_bf16.h>
#include <cuda_fp16.h>
#include <cstdint>
#include <math.h>

// Problem constants
#define BATCH 8
#define SEQ   1024
#define HID   768
#define NHEAD 12
#define DHEAD 64
#define ROWS  (BATCH*SEQ)          // 8192
#define FF    (2*HID)              // 1536
#define NQKV  (3*HID)              // 2304

// ---------------- scratch (device globals; no allocations allowed) ----------
__device__ float g_ctx[ROWS*HID];
__device__ float g_x  [ROWS*HID];
__device__ float g_ff2[ROWS*HID];
__device__ float g_bqkv[NQKV];

__device__ __half g_qkv16[ROWS*NQKV];  // q(pre-scaled 1/8) | k | v, fp16
__device__ __half g_ah[ROWS*HID];      // fp16 activations (A inputs)
__device__ __half g_fh[ROWS*FF];       // fp16 ff1 output (A for ff2)
__device__ __half g_wqkvh[NQKV*HID];   // W^T fp16, rows = N, K-major
__device__ __half g_w1h[FF*HID];
__device__ __half g_w2h[HID*FF];

// ---------------- PTX helpers (sm_80-era only; no 'a'-features) -------------
__device__ __forceinline__ uint32_t smem_u32(const void* p) {
    uint32_t a;
    asm("{ .reg .u64 t; cvta.to.shared.u64 t, %1; cvt.u32.u64 %0, t; }"
        : "=r"(a) : "l"(p));
    return a;
}

__device__ __forceinline__ void cp16(uint32_t dst, const void* src) {
    asm volatile("cp.async.cg.shared.global [%0], [%1], 16;"
                 :: "r"(dst), "l"(src));
}
#define CP_COMMIT() asm volatile("cp.async.commit_group;" ::: "memory")
#define CP_WAIT(n)  asm volatile("cp.async.wait_group %0;" :: "n"(n) : "memory")

__device__ __forceinline__ void ldsm4(uint32_t& r0, uint32_t& r1,
                                      uint32_t& r2, uint32_t& r3, uint32_t addr) {
    asm volatile("ldmatrix.sync.aligned.m8n8.x4.shared.b16 {%0,%1,%2,%3}, [%4];"
                 : "=r"(r0), "=r"(r1), "=r"(r2), "=r"(r3) : "r"(addr));
}

__device__ __forceinline__ void mma_f16(float* c, const uint32_t* a, const uint32_t* b) {
    asm volatile("mma.sync.aligned.m16n8k16.row.col.f32.f16.f16.f32 "
                 "{%0,%1,%2,%3}, {%4,%5,%6,%7}, {%8,%9}, {%0,%1,%2,%3};"
                 : "+f"(c[0]), "+f"(c[1]), "+f"(c[2]), "+f"(c[3])
                 : "r"(a[0]), "r"(a[1]), "r"(a[2]), "r"(a[3]),
                   "r"(b[0]), "r"(b[1]));
}

__device__ __forceinline__ uint32_t packh(float x, float y) {
    __half2 p = __floats2half2_rn(x, y);
    return *(uint32_t*)&p;
}

// ---------------- prep kernels ----------------------------------------------
__global__ void prep_bias(const float* __restrict__ bq, const float* __restrict__ bk,
                          const float* __restrict__ bv) {
    int i = blockIdx.x * blockDim.x + threadIdx.x;
    if (i < HID) {
        g_bqkv[i]         = bq[i];
        g_bqkv[i + HID]   = bk[i];
        g_bqkv[i + 2*HID] = bv[i];
    }
}

// W[K,N] fp32 -> out[N,K] fp16 (transpose + convert)
__device__ __forceinline__ void tsp_body(const float* __restrict__ W,
                                         __half* __restrict__ oh,
                                         int K, int N) {
    __shared__ float t[32][33];
    const int tx = threadIdx.x, ty = threadIdx.y;
    const int n0 = blockIdx.x * 32, k0 = blockIdx.y * 32;
#pragma unroll
    for (int i = 0; i < 4; i++)
        t[ty + 8*i][tx] = W[(size_t)(k0 + ty + 8*i) * N + n0 + tx];
    __syncthreads();
#pragma unroll
    for (int i = 0; i < 4; i++) {
        float v = t[tx][ty + 8*i];
        oh[(size_t)(n0 + ty + 8*i) * K + k0 + tx] = __float2half_rn(v);
    }
}

__global__ void __launch_bounds__(256)
transpose_conv(const float* __restrict__ W, __half* __restrict__ oh, int K, int N) {
    tsp_body(W, oh, K, N);
}

__global__ void __launch_bounds__(256)
transpose_qkv(const float* __restrict__ Wq, const float* __restrict__ Wk,
              const float* __restrict__ Wv) {
    const float* W = (blockIdx.z == 0) ? Wq : (blockIdx.z == 1) ? Wk : Wv;
    tsp_body(W, g_wqkvh + (size_t)blockIdx.z * HID * HID, HID, HID);
}

// fp32 -> fp16 elementwise
__global__ void __launch_bounds__(256)
convert_half(const float* __restrict__ in, __half* __restrict__ oh, int n4) {
    for (int i = blockIdx.x * blockDim.x + threadIdx.x; i < n4;
         i += gridDim.x * blockDim.x) {
        float4 a = ((const float4*)in)[i];
        ((__half2*)oh)[2*i]   = __floats2half2_rn(a.x, a.y);
        ((__half2*)oh)[2*i+1] = __floats2half2_rn(a.z, a.w);
    }
}

// ---------------- fp16 single-pass mma.sync GEMM (128x128, 4-stage, occ 2) ---
// mode 0: fp32 out. mode 1: fp16 out. mode 2 (QKV): fp16 out, q cols scaled 1/8.
#define ASTR    40
#define STGB    (128 * ASTR * 2)
#define STAGES  4
#define GEMM_SMEM (STAGES * 2 * STGB)        // 81920 B

__global__ void __launch_bounds__(256, 2)
gemm_mma(const __half* __restrict__ A, const __half* __restrict__ B,
         const float* __restrict__ bias,
         float* __restrict__ Cf, __half* __restrict__ Ch,
         int N, int K, int relu, int mode)
{
    extern __shared__ __align__(16) char dsm[];
    __half* smA = (__half*)dsm;
    __half* smB = (__half*)(dsm + STAGES * STGB);

    const int tid  = threadIdx.x;
    const int wid  = tid >> 5, lane = tid & 31;
    const int warp_m = wid >> 2;
    const int warp_n = wid & 3;
    const int m0 = blockIdx.y << 7;
    const int n0 = blockIdx.x << 7;

    const uint32_t sA = smem_u32(smA);
    const uint32_t sB = smem_u32(smB);

    const int lrow  = tid >> 1;
    const int lcolh = (tid & 1) * 16;

    const int kb = K >> 5;

    float c[4][4][4];
#pragma unroll
    for (int i = 0; i < 4; i++)
#pragma unroll
        for (int j = 0; j < 4; j++)
#pragma unroll
            for (int r = 0; r < 4; r++) c[i][j][r] = 0.f;

    const int rowoff = ((lane >> 3) & 1) * 8 + (lane & 7);
    const int coloff = ((lane >> 4) & 1) * 8;

    auto issue = [&](int blk) {
        if (blk < kb) {
            const __half* ga = A + (size_t)(m0 + lrow) * K + blk * 32 + lcolh;
            const __half* gb = B + (size_t)(n0 + lrow) * K + blk * 32 + lcolh;
            int st = blk & (STAGES - 1);
            uint32_t da = sA + st * STGB + (lrow * ASTR + lcolh) * 2;
            uint32_t db = sB + st * STGB + (lrow * ASTR + lcolh) * 2;
            cp16(da,      ga);
            cp16(da + 16, ga + 8);
            cp16(db,      gb);
            cp16(db + 16, gb + 8);
        }
        CP_COMMIT();
    };

    issue(0); issue(1); issue(2);

    for (int blk = 0; blk < kb; blk++) {
        CP_WAIT(2);
        __syncthreads();

        const int stage = blk & (STAGES - 1);
        const uint32_t a0 = sA + stage * STGB;
        const uint32_t b0 = sB + stage * STGB;
#pragma unroll
        for (int kh = 0; kh < 2; kh++) {
            uint32_t af[4][4];
#pragma unroll
            for (int t = 0; t < 4; t++)
                ldsm4(af[t][0], af[t][1], af[t][2], af[t][3],
                      a0 + ((warp_m * 64 + t * 16 + rowoff) * ASTR + kh * 16 + coloff) * 2);
            uint32_t bf[4][2];
#pragma unroll
            for (int p = 0; p < 2; p++) {
                uint32_t r0, r1, r2, r3;
                ldsm4(r0, r1, r2, r3,
                      b0 + ((warp_n * 32 + p * 16 + rowoff) * ASTR + kh * 16 + coloff) * 2);
                bf[2*p][0]   = r0; bf[2*p][1]   = r2;
                bf[2*p+1][0] = r1; bf[2*p+1][1] = r3;
            }
#pragma unroll
            for (int i = 0; i < 4; i++)
#pragma unroll
                for (int j = 0; j < 4; j++)
                    mma_f16(c[i][j], af[i], bf[j]);
        }
        issue(blk + 3);
    }

    const float qsc = (mode == 2 && n0 < HID) ? 0.125f : 1.0f;

#pragma unroll
    for (int i = 0; i < 4; i++) {
#pragma unroll
        for (int j = 0; j < 4; j++) {
            int grow = m0 + warp_m * 64 + i * 16 + (lane >> 2);
            int gcol = n0 + warp_n * 32 + j * 8 + (lane & 3) * 2;
            float b0v = bias[gcol], b1v = bias[gcol + 1];
            float v0 = c[i][j][0] + b0v;
            float v1 = c[i][j][1] + b1v;
            float v2 = c[i][j][2] + b0v;
            float v3 = c[i][j][3] + b1v;
            if (relu) {
                v0 = fmaxf(v0, 0.f); v1 = fmaxf(v1, 0.f);
                v2 = fmaxf(v2, 0.f); v3 = fmaxf(v3, 0.f);
            }
            if (mode == 0) {
                *(float2*)(Cf + (size_t)grow * N + gcol)       = make_float2(v0, v1);
                *(float2*)(Cf + (size_t)(grow + 8) * N + gcol) = make_float2(v2, v3);
            } else {
                __half2 p0 = __floats2half2_rn(v0 * qsc, v1 * qsc);
                __half2 p1 = __floats2half2_rn(v2 * qsc, v3 * qsc);
                *(__half2*)(Ch + (size_t)grow * N + gcol)       = p0;
                *(__half2*)(Ch + (size_t)(grow + 8) * N + gcol) = p1;
            }
        }
    }
}

// ---------------- tensor-core flash attention (fp16, double-buffered K/V) ----
// One __syncthreads per k-tile; staging (incl. V transpose) overlaps compute.
#define QT 128
#define KTILE 64
#define SQ 72
#define ATTN_SMEM ((QT + 4*KTILE) * SQ * 2)    // 55296 B

__global__ void __launch_bounds__(256, 2)
attn_mma(const float* __restrict__ wm)
{
    extern __shared__ __align__(16) __half am_[];
    __half* qs = am_;                     // [row][d]
    __half* ks = qs + QT * SQ;            // 2 x [k][d]
    __half* vt = ks + 2 * KTILE * SQ;     // 2 x [d][k]

    const int tid = threadIdx.x, wid = tid >> 5, lane = tid & 31;
    const int b = blockIdx.z, h = blockIdx.y, q0 = blockIdx.x * QT;

    const uint32_t sqs = smem_u32(qs);
    const uint32_t sks = smem_u32(ks);
    const uint32_t svt = smem_u32(vt);

    const int krow = tid >> 2, kcb = (tid & 3) * 16;

    // stage helper: write K (copy) and V (transposed) from regs into buffer `buf`
    auto stage = [&](int buf, const uint4* rk, const uint4* rv) {
        __half* kd = ks + buf * KTILE * SQ;
        __half* vd = vt + buf * KTILE * SQ;
        *(uint4*)(kd + krow * SQ + kcb)     = rk[0];
        *(uint4*)(kd + krow * SQ + kcb + 8) = rk[1];
        __half vv[16];
        *(uint4*)vv       = rv[0];
        *(uint4*)(vv + 8) = rv[1];
#pragma unroll
        for (int e = 0; e < 16; e++)
            vd[(kcb + e) * SQ + krow] = vv[e];
    };
    auto fetch = [&](int kt, uint4* rk, uint4* rv) {
        const __half* kp = g_qkv16 + (size_t)(b * SEQ + kt * KTILE + krow) * NQKV
                           + HID + h * DHEAD + kcb;
        rk[0] = *(const uint4*)kp;          rk[1] = *(const uint4*)(kp + 8);
        rv[0] = *(const uint4*)(kp + HID);  rv[1] = *(const uint4*)(kp + HID + 8);
    };

    // ---- prologue: stage Q, stage K/V tile 0, prefetch tile 1 ----
    {
        const int row = tid >> 1, cb = (tid & 1) * 32;
        const __half* src = g_qkv16 + (size_t)(b * SEQ + q0 + row) * NQKV + h * DHEAD + cb;
#pragma unroll
        for (int f = 0; f < 4; f++)
            *(uint4*)(qs + row * SQ + cb + 8 * f) = *(const uint4*)(src + 8 * f);
    }
    uint4 rk[2], rv[2];
    fetch(0, rk, rv);
    stage(0, rk, rv);
    fetch(1, rk, rv);
    __syncthreads();

    float m0 = -1e30f, m1 = -1e30f, l0 = 0.f, l1 = 0.f;
    float o[8][4];
#pragma unroll
    for (int j = 0; j < 8; j++)
#pragma unroll
        for (int r = 0; r < 4; r++) o[j][r] = 0.f;

    const int rowoff = ((lane >> 3) & 1) * 8 + (lane & 7);
    const int coloff = (lane >> 4) * 8;
    const int rA = q0 + wid * 16 + (lane >> 2);

    for (int kt = 0; kt < 16; kt++) {
        const int cur = kt & 1;
        // stage tile kt+1 into the inactive buffer (overlaps this tile's compute)
        if (kt < 15) stage(1 - cur, rk, rv);
        if (kt + 2 < 16) fetch(kt + 2, rk, rv);

        // mask tile (fp32, hidden under QK MMAs)
        float2 mk0[8], mk1[8];
        {
            const float* mr0 = wm + ((size_t)b * SEQ + rA) * SEQ + kt * KTILE + (lane & 3) * 2;
            const float* mr1 = mr0 + 8 * SEQ;
#pragma unroll
            for (int j = 0; j < 8; j++) {
                mk0[j] = *(const float2*)(mr0 + 8 * j);
                mk1[j] = *(const float2*)(mr1 + 8 * j);
            }
        }

        const uint32_t kbase = sks + (uint32_t)(cur * KTILE * SQ) * 2;
        const uint32_t vbase = svt + (uint32_t)(cur * KTILE * SQ) * 2;

        // ---- QK^T ----
        float s[8][4];
#pragma unroll
        for (int j = 0; j < 8; j++)
#pragma unroll
            for (int r = 0; r < 4; r++) s[j][r] = 0.f;

#pragma unroll
        for (int t = 0; t < 4; t++) {
            uint32_t af[4];
            ldsm4(af[0], af[1], af[2], af[3],
                  sqs + ((wid * 16 + rowoff) * SQ + t * 16 + coloff) * 2);
#pragma unroll
            for (int p = 0; p < 4; p++) {
                uint32_t r0, r1, r2, r3;
                ldsm4(r0, r1, r2, r3,
                      kbase + ((p * 16 + rowoff) * SQ + t * 16 + coloff) * 2);
                uint32_t b0[2] = {r0, r2}, b1[2] = {r1, r3};
                mma_f16(s[2*p],   af, b0);
                mma_f16(s[2*p+1], af, b1);
            }
        }

        // ---- online softmax (denominator UNmasked), then mask ----
        float lm0 = -1e30f, lm1 = -1e30f;
#pragma unroll
        for (int j = 0; j < 8; j++) {
            lm0 = fmaxf(lm0, fmaxf(s[j][0], s[j][1]));
            lm1 = fmaxf(lm1, fmaxf(s[j][2], s[j][3]));
        }
        lm0 = fmaxf(lm0, __shfl_xor_sync(0xffffffffu, lm0, 1));
        lm0 = fmaxf(lm0, __shfl_xor_sync(0xffffffffu, lm0, 2));
        lm1 = fmaxf(lm1, __shfl_xor_sync(0xffffffffu, lm1, 1));
        lm1 = fmaxf(lm1, __shfl_xor_sync(0xffffffffu, lm1, 2));
        float mn0 = fmaxf(m0, lm0), mn1 = fmaxf(m1, lm1);
        float f0 = __expf(m0 - mn0), f1 = __expf(m1 - mn1);
        m0 = mn0; m1 = mn1;
        float ls0 = 0.f, ls1 = 0.f;
#pragma unroll
        for (int j = 0; j < 8; j++) {
            float e0 = __expf(s[j][0] - mn0);
            float e1 = __expf(s[j][1] - mn0);
            float e2 = __expf(s[j][2] - mn1);
            float e3 = __expf(s[j][3] - mn1);
            ls0 += e0 + e1; ls1 += e2 + e3;
            s[j][0] = e0 * mk0[j].x;
            s[j][1] = e1 * mk0[j].y;
            s[j][2] = e2 * mk1[j].x;
            s[j][3] = e3 * mk1[j].y;
        }
        ls0 += __shfl_xor_sync(0xffffffffu, ls0, 1);
        ls0 += __shfl_xor_sync(0xffffffffu, ls0, 2);
        ls1 += __shfl_xor_sync(0xffffffffu, ls1, 1);
        ls1 += __shfl_xor_sync(0xffffffffu, ls1, 2);
        l0 = l0 * f0 + ls0;
        l1 = l1 * f1 + ls1;
#pragma unroll
        for (int j = 0; j < 8; j++) {
            o[j][0] *= f0; o[j][1] *= f0;
            o[j][2] *= f1; o[j][3] *= f1;
        }

        // ---- PV ----
#pragma unroll
        for (int u = 0; u < 4; u++) {
            uint32_t pa[4];
            pa[0] = packh(s[2*u][0],   s[2*u][1]);
            pa[1] = packh(s[2*u][2],   s[2*u][3]);
            pa[2] = packh(s[2*u+1][0], s[2*u+1][1]);
            pa[3] = packh(s[2*u+1][2], s[2*u+1][3]);
#pragma unroll
            for (int p = 0; p < 4; p++) {
                uint32_t r0, r1, r2, r3;
                ldsm4(r0, r1, r2, r3,
                      vbase + ((p * 16 + rowoff) * SQ + u * 16 + coloff) * 2);
                uint32_t b0[2] = {r0, r2}, b1[2] = {r1, r3};
                mma_f16(o[2*p],   pa, b0);
                mma_f16(o[2*p+1], pa, b1);
            }
        }
        __syncthreads();
    }

    float inv0 = 1.0f / l0, inv1 = 1.0f / l1;
    float* c0 = g_ctx + ((size_t)(b * SEQ) + rA) * HID + h * DHEAD + (lane & 3) * 2;
    float* c1 = c0 + 8 * HID;
#pragma unroll
    for (int j = 0; j < 8; j++) {
        *(float2*)(c0 + 8 * j) = make_float2(o[j][0] * inv0, o[j][1] * inv0);
        *(float2*)(c1 + 8 * j) = make_float2(o[j][2] * inv1, o[j][3] * inv1);
    }
}

// ---------------- fused residual-add + LayerNorm -----------------------------
// ln1: residual q read from g_qkv16 fp16 (pre-scaled 1/8 -> rescale x8, exact pow2).
__global__ void __launch_bounds__(256)
ln1_kernel(const float* __restrict__ g, const float* __restrict__ be)
{
    const int row = blockIdx.x;
    const int tid = threadIdx.x;
    __shared__ float red[8];
    __shared__ float s_mu, s_rs;

    float4 v4 = make_float4(0.f, 0.f, 0.f, 0.f);
    float ls = 0.f;
    if (tid < 192) {
        float4 av = ((const float4*)(g_ctx + (size_t)row * HID))[tid];
        const __half2* qp = (const __half2*)(g_qkv16 + (size_t)row * NQKV);
        float2 q0 = __half22float2(qp[2*tid]);
        float2 q1 = __half22float2(qp[2*tid+1]);
        v4 = make_float4(av.x + 8.f*q0.x, av.y + 8.f*q0.y,
                         av.z + 8.f*q1.x, av.w + 8.f*q1.y);
        ls = v4.x + v4.y + v4.z + v4.w;
    }
    int lane = tid & 31, wid = tid >> 5;
#pragma unroll
    for (int o = 16; o; o >>= 1) ls += __shfl_xor_sync(0xffffffffu, ls, o);
    if (lane == 0) red[wid] = ls;
    __syncthreads();
    if (tid == 0) {
        float t = 0.f;
#pragma unroll
        for (int i = 0; i < 8; i++) t += red[i];
        s_mu = t * (1.0f / HID);
    }
    __syncthreads();
    float mu = s_mu;

    float4 dx = make_float4(v4.x - mu, v4.y - mu, v4.z - mu, v4.w - mu);
    float lv = 0.f;
    if (tid < 192)
        lv = dx.x * dx.x + dx.y * dx.y + dx.z * dx.z + dx.w * dx.w;
#pragma unroll
    for (int o = 16; o; o >>= 1) lv += __shfl_xor_sync(0xffffffffu, lv, o);
    __syncthreads();
    if (lane == 0) red[wid] = lv;
    __syncthreads();
    if (tid == 0) {
        float t = 0.f;
#pragma unroll
        for (int i = 0; i < 8; i++) t += red[i];
        s_rs = rsqrtf(t * (1.0f / HID) + 1e-5f);
    }
    __syncthreads();
    float rs = s_rs;

    if (tid < 192) {
        float4 g4  = ((const float4*)g)[tid];
        float4 be4 = ((const float4*)be)[tid];
        float4 o = make_float4(dx.x * rs * g4.x + be4.x,
                               dx.y * rs * g4.y + be4.y,
                               dx.z * rs * g4.z + be4.z,
                               dx.w * rs * g4.w + be4.w);
        ((float4*)(g_x + (size_t)row * HID))[tid] = o;
        ((__half2*)(g_ah + (size_t)row * HID))[2*tid]   = __floats2half2_rn(o.x, o.y);
        ((__half2*)(g_ah + (size_t)row * HID))[2*tid+1] = __floats2half2_rn(o.z, o.w);
    }
}

__global__ void __launch_bounds__(256)
ln2_kernel(const float* __restrict__ g, const float* __restrict__ be,
           float* __restrict__ out)
{
    const int row = blockIdx.x;
    const int tid = threadIdx.x;
    __shared__ float red[8];
    __shared__ float s_mu, s_rs;

    float4 v4 = make_float4(0.f, 0.f, 0.f, 0.f);
    float ls = 0.f;
    if (tid < 192) {
        float4 av = ((const float4*)(g_x   + (size_t)row * HID))[tid];
        float4 bv = ((const float4*)(g_ff2 + (size_t)row * HID))[tid];
        v4 = make_float4(av.x + bv.x, av.y + bv.y, av.z + bv.z, av.w + bv.w);
        ls = v4.x + v4.y + v4.z + v4.w;
    }
    int lane = tid & 31, wid = tid >> 5;
#pragma unroll
    for (int o = 16; o; o >>= 1) ls += __shfl_xor_sync(0xffffffffu, ls, o);
    if (lane == 0) red[wid] = ls;
    __syncthreads();
    if (tid == 0) {
        float t = 0.f;
#pragma unroll
        for (int i = 0; i < 8; i++) t += red[i];
        s_mu = t * (1.0f / HID);
    }
    __syncthreads();
    float mu = s_mu;

    float4 dx = make_float4(v4.x - mu, v4.y - mu, v4.z - mu, v4.w - mu);
    float lv = 0.f;
    if (tid < 192)
        lv = dx.x * dx.x + dx.y * dx.y + dx.z * dx.z + dx.w * dx.w;
#pragma unroll
    for (int o = 16; o; o >>= 1) lv += __shfl_xor_sync(0xffffffffu, lv, o);
    __syncthreads();
    if (lane == 0) red[wid] = lv;
    __syncthreads();
    if (tid == 0) {
        float t = 0.f;
#pragma unroll
        for (int i = 0; i < 8; i++) t += red[i];
        s_rs = rsqrtf(t * (1.0f / HID) + 1e-5f);
    }
    __syncthreads();
    float rs = s_rs;

    if (tid < 192) {
        float4 g4  = ((const float4*)g)[tid];
        float4 be4 = ((const float4*)be)[tid];
        float4 o = make_float4(dx.x * rs * g4.x + be4.x,
                               dx.y * rs * g4.y + be4.y,
                               dx.z * rs * g4.z + be4.z,
                               dx.w * rs * g4.w + be4.w);
        ((float4*)(out + (size_t)row * HID))[tid] = o;
    }
}

// ---------------- launch -----------------------------------------------------
extern "C" void kernel_launch(void* const* d_in, const int* in_sizes, int n_in,
                              void* d_out, int out_size)
{
    const float* x1  = (const float*)d_in[0];
    const float* wm  = (const float*)d_in[1];
    const float* Wq  = (const float*)d_in[2];
    const float* bq  = (const float*)d_in[3];
    const float* Wk  = (const float*)d_in[4];
    const float* bk  = (const float*)d_in[5];
    const float* Wv  = (const float*)d_in[6];
    const float* bv  = (const float*)d_in[7];
    const float* g1  = (const float*)d_in[8];
    const float* be1 = (const float*)d_in[9];
    const float* g2  = (const float*)d_in[10];
    const float* be2 = (const float*)d_in[11];
    const float* W1  = (const float*)d_in[12];
    const float* b1  = (const float*)d_in[13];
    const float* W2  = (const float*)d_in[14];
    const float* b2  = (const float*)d_in[15];
    float* out = (float*)d_out;

    void *p_ah, *p_fh, *p_w1h, *p_w2h;
    void *p_qkv16, *p_bqkv, *p_ff2, *p_wqh;
    cudaGetSymbolAddress(&p_ah, g_ah);
    cudaGetSymbolAddress(&p_fh, g_fh);
    cudaGetSymbolAddress(&p_w1h, g_w1h);
    cudaGetSymbolAddress(&p_w2h, g_w2h);
    cudaGetSymbolAddress(&p_qkv16, g_qkv16);
    cudaGetSymbolAddress(&p_bqkv, g_bqkv);
    cudaGetSymbolAddress(&p_ff2, g_ff2);
    cudaGetSymbolAddress(&p_wqh, g_wqkvh);

    __half* ah    = (__half*)p_ah;
    __half* fh    = (__half*)p_fh;
    __half* wqh   = (__half*)p_wqh;
    __half* w1h   = (__half*)p_w1h;
    __half* w2h   = (__half*)p_w2h;
    __half* qkv16 = (__half*)p_qkv16;
    float* bqkv   = (float*)p_bqkv;
    float* ff2    = (float*)p_ff2;

    cudaFuncSetAttribute(attn_mma,
                         cudaFuncAttributeMaxDynamicSharedMemorySize, ATTN_SMEM);
    cudaFuncSetAttribute(gemm_mma,
                         cudaFuncAttributeMaxDynamicSharedMemorySize, GEMM_SMEM);

    dim3 tb(32, 8);

    // weight prep
    prep_bias<<<3, 256>>>(bq, bk, bv);
    transpose_qkv<<<dim3(HID/32, HID/32, 3), tb>>>(Wq, Wk, Wv);
    transpose_conv<<<dim3(FF/32,  HID/32), tb>>>(W1, w1h, HID, FF);
    transpose_conv<<<dim3(HID/32, FF/32),  tb>>>(W2, w2h, FF, HID);

    // x1 -> fp16
    convert_half<<<2048, 256>>>(x1, ah, ROWS * HID / 4);

    // fused QKV GEMM: fp16 out, q pre-scaled 1/8 (mode 2)
    gemm_mma<<<dim3(NQKV/128, ROWS/128), 256, GEMM_SMEM>>>(
        ah, wqh, bqkv, nullptr, qkv16, NQKV, HID, 0, 2);

    // fp16 flash attention with post-softmax mask (double-buffered K/V)
    attn_mma<<<dim3(SEQ/QT, NHEAD, BATCH), 256, ATTN_SMEM>>>(wm);

    // x = LN(ctx + q_mixed), q reconstructed from fp16 (x8), fused fp16 emit
    ln1_kernel<<<ROWS, 256>>>(g1, be1);

    // ff1 = relu(x @ W1 + b1) -> fp16
    gemm_mma<<<dim3(FF/128, ROWS/128), 256, GEMM_SMEM>>>(
        ah, w1h, b1, nullptr, fh, FF, HID, 1, 1);

    // ff2 = ff1 @ W2 + b2 -> fp32
    gemm_mma<<<dim3(HID/128, ROWS/128), 256, GEMM_SMEM>>>(
        fh, w2h, b2, ff2, nullptr, HID, FF, 0, 0);

    // out = LN(x + ff2)
    ln2_kernel<<<ROWS, 256>>>(g2, be2, out);
}

// round 15
// speedup vs baseline: 1.0169x; 1.0169x over previous
#include <cuda_runtime.h>
#include <cuda_bf16.h>
#include <cuda_fp16.h>
#include <cstdint>
#include <math.h>

// Problem constants
#define BATCH 8
#define SEQ   1024
#define HID   768
#define NHEAD 12
#define DHEAD 64
#define ROWS  (BATCH*SEQ)          // 8192
#define FF    (2*HID)              // 1536
#define NQKV  (3*HID)              // 2304

// ---------------- scratch (device globals; no allocations allowed) ----------
__device__ float g_ctx[ROWS*HID];
__device__ float g_x  [ROWS*HID];
__device__ float g_ff2[ROWS*HID];
__device__ float g_bqkv[NQKV];

__device__ __half g_qkv16[ROWS*NQKV];  // q(pre-scaled 1/8) | k | v, fp16
__device__ __half g_ah[ROWS*HID];      // fp16 activations (A inputs)
__device__ __half g_fh[ROWS*FF];       // fp16 ff1 output (A for ff2)
__device__ __half g_wqkvh[NQKV*HID];   // W^T fp16, rows = N, K-major
__device__ __half g_w1h[FF*HID];
__device__ __half g_w2h[HID*FF];

// ---------------- PTX helpers (sm_80-era only; no 'a'-features) -------------
__device__ __forceinline__ uint32_t smem_u32(const void* p) {
    uint32_t a;
    asm("{ .reg .u64 t; cvta.to.shared.u64 t, %1; cvt.u32.u64 %0, t; }"
        : "=r"(a) : "l"(p));
    return a;
}

__device__ __forceinline__ void cp16(uint32_t dst, const void* src) {
    asm volatile("cp.async.cg.shared.global [%0], [%1], 16;"
                 :: "r"(dst), "l"(src));
}
#define CP_COMMIT() asm volatile("cp.async.commit_group;" ::: "memory")
#define CP_WAIT(n)  asm volatile("cp.async.wait_group %0;" :: "n"(n) : "memory")

__device__ __forceinline__ void ldsm4(uint32_t& r0, uint32_t& r1,
                                      uint32_t& r2, uint32_t& r3, uint32_t addr) {
    asm volatile("ldmatrix.sync.aligned.m8n8.x4.shared.b16 {%0,%1,%2,%3}, [%4];"
                 : "=r"(r0), "=r"(r1), "=r"(r2), "=r"(r3) : "r"(addr));
}

__device__ __forceinline__ void mma_f16(float* c, const uint32_t* a, const uint32_t* b) {
    asm volatile("mma.sync.aligned.m16n8k16.row.col.f32.f16.f16.f32 "
                 "{%0,%1,%2,%3}, {%4,%5,%6,%7}, {%8,%9}, {%0,%1,%2,%3};"
                 : "+f"(c[0]), "+f"(c[1]), "+f"(c[2]), "+f"(c[3])
                 : "r"(a[0]), "r"(a[1]), "r"(a[2]), "r"(a[3]),
                   "r"(b[0]), "r"(b[1]));
}

__device__ __forceinline__ uint32_t packh(float x, float y) {
    __half2 p = __floats2half2_rn(x, y);
    return *(uint32_t*)&p;
}

// ---------------- fused prep kernel ------------------------------------------
// One launch does: Wq/Wk/Wv transpose (1728 blocks), W1 (1152), W2 (1152),
// bias gather (3), x1 fp32->fp16 convert (2048). All regions independent.
#define NB_QKV  1728                        // 3 * 24 * 24
#define NB_W1   1152                        // 48 * 24
#define NB_W2   1152                        // 24 * 48
#define NB_BIAS 3
#define NB_CVT  2048
#define NB_PREP (NB_QKV + NB_W1 + NB_W2 + NB_BIAS + NB_CVT)  // 6083

__device__ __forceinline__ void tsp_tile(const float* __restrict__ W,
                                         __half* __restrict__ oh,
                                         int K, int N, int n0, int k0) {
    __shared__ float t[32][33];
    const int tx = threadIdx.x & 31, ty = threadIdx.x >> 5;
#pragma unroll
    for (int i = 0; i < 4; i++)
        t[ty + 8*i][tx] = W[(size_t)(k0 + ty + 8*i) * N + n0 + tx];
    __syncthreads();
#pragma unroll
    for (int i = 0; i < 4; i++) {
        float v = t[tx][ty + 8*i];
        oh[(size_t)(n0 + ty + 8*i) * K + k0 + tx] = __float2half_rn(v);
    }
}

__global__ void __launch_bounds__(256)
prep_all(const float* __restrict__ x1,
         const float* __restrict__ Wq, const float* __restrict__ Wk,
         const float* __restrict__ Wv,
         const float* __restrict__ W1, const float* __restrict__ W2,
         const float* __restrict__ bq, const float* __restrict__ bk,
         const float* __restrict__ bv)
{
    const int bid = blockIdx.x;
    const int tid = threadIdx.x;

    if (bid < NB_QKV) {
        const int z = bid / 576, r = bid % 576;
        const int n0 = (r % 24) * 32, k0 = (r / 24) * 32;
        const float* W = (z == 0) ? Wq : (z == 1) ? Wk : Wv;
        tsp_tile(W, g_wqkvh + (size_t)z * HID * HID, HID, HID, n0, k0);
    } else if (bid < NB_QKV + NB_W1) {
        const int r = bid - NB_QKV;
        const int n0 = (r % 48) * 32, k0 = (r / 48) * 32;   // N=FF, K=HID
        tsp_tile(W1, g_w1h, HID, FF, n0, k0);
    } else if (bid < NB_QKV + NB_W1 + NB_W2) {
        const int r = bid - (NB_QKV + NB_W1);
        const int n0 = (r % 24) * 32, k0 = (r / 24) * 32;   // N=HID, K=FF
        tsp_tile(W2, g_w2h, FF, HID, n0, k0);
    } else if (bid < NB_QKV + NB_W1 + NB_W2 + NB_BIAS) {
        const int i = (bid - (NB_QKV + NB_W1 + NB_W2)) * 256 + tid;
        if (i < HID) {
            g_bqkv[i]         = bq[i];
            g_bqkv[i + HID]   = bk[i];
            g_bqkv[i + 2*HID] = bv[i];
        }
    } else {
        const int cb = bid - (NB_QKV + NB_W1 + NB_W2 + NB_BIAS);
        const int n4 = ROWS * HID / 4;
        for (int i = cb * 256 + tid; i < n4; i += NB_CVT * 256) {
            float4 a = ((const float4*)x1)[i];
            ((__half2*)g_ah)[2*i]   = __floats2half2_rn(a.x, a.y);
            ((__half2*)g_ah)[2*i+1] = __floats2half2_rn(a.z, a.w);
        }
    }
}

// ---------------- fp16 single-pass mma.sync GEMM (128x128, 4-stage, occ 2) ---
// mode 0: fp32 out. mode 1: fp16 out. mode 2 (QKV): fp16 out, q cols scaled 1/8.
#define ASTR    40
#define STGB    (128 * ASTR * 2)
#define STAGES  4
#define GEMM_SMEM (STAGES * 2 * STGB)        // 81920 B

__global__ void __launch_bounds__(256, 2)
gemm_mma(const __half* __restrict__ A, const __half* __restrict__ B,
         const float* __restrict__ bias,
         float* __restrict__ Cf, __half* __restrict__ Ch,
         int N, int K, int relu, int mode)
{
    extern __shared__ __align__(16) char dsm[];
    __half* smA = (__half*)dsm;
    __half* smB = (__half*)(dsm + STAGES * STGB);

    const int tid  = threadIdx.x;
    const int wid  = tid >> 5, lane = tid & 31;
    const int warp_m = wid >> 2;
    const int warp_n = wid & 3;
    const int m0 = blockIdx.y << 7;
    const int n0 = blockIdx.x << 7;

    const uint32_t sA = smem_u32(smA);
    const uint32_t sB = smem_u32(smB);

    const int lrow  = tid >> 1;
    const int lcolh = (tid & 1) * 16;

    const int kb = K >> 5;

    float c[4][4][4];
#pragma unroll
    for (int i = 0; i < 4; i++)
#pragma unroll
        for (int j = 0; j < 4; j++)
#pragma unroll
            for (int r = 0; r < 4; r++) c[i][j][r] = 0.f;

    const int rowoff = ((lane >> 3) & 1) * 8 + (lane & 7);
    const int coloff = ((lane >> 4) & 1) * 8;

    auto issue = [&](int blk) {
        if (blk < kb) {
            const __half* ga = A + (size_t)(m0 + lrow) * K + blk * 32 + lcolh;
            const __half* gb = B + (size_t)(n0 + lrow) * K + blk * 32 + lcolh;
            int st = blk & (STAGES - 1);
            uint32_t da = sA + st * STGB + (lrow * ASTR + lcolh) * 2;
            uint32_t db = sB + st * STGB + (lrow * ASTR + lcolh) * 2;
            cp16(da,      ga);
            cp16(da + 16, ga + 8);
            cp16(db,      gb);
            cp16(db + 16, gb + 8);
        }
        CP_COMMIT();
    };

    issue(0); issue(1); issue(2);

    for (int blk = 0; blk < kb; blk++) {
        CP_WAIT(2);
        __syncthreads();

        const int stage = blk & (STAGES - 1);
        const uint32_t a0 = sA + stage * STGB;
        const uint32_t b0 = sB + stage * STGB;
#pragma unroll
        for (int kh = 0; kh < 2; kh++) {
            uint32_t af[4][4];
#pragma unroll
            for (int t = 0; t < 4; t++)
                ldsm4(af[t][0], af[t][1], af[t][2], af[t][3],
                      a0 + ((warp_m * 64 + t * 16 + rowoff) * ASTR + kh * 16 + coloff) * 2);
            uint32_t bf[4][2];
#pragma unroll
            for (int p = 0; p < 2; p++) {
                uint32_t r0, r1, r2, r3;
                ldsm4(r0, r1, r2, r3,
                      b0 + ((warp_n * 32 + p * 16 + rowoff) * ASTR + kh * 16 + coloff) * 2);
                bf[2*p][0]   = r0; bf[2*p][1]   = r2;
                bf[2*p+1][0] = r1; bf[2*p+1][1] = r3;
            }
#pragma unroll
            for (int i = 0; i < 4; i++)
#pragma unroll
                for (int j = 0; j < 4; j++)
                    mma_f16(c[i][j], af[i], bf[j]);
        }
        issue(blk + 3);
    }

    const float qsc = (mode == 2 && n0 < HID) ? 0.125f : 1.0f;

#pragma unroll
    for (int i = 0; i < 4; i++) {
#pragma unroll
        for (int j = 0; j < 4; j++) {
            int grow = m0 + warp_m * 64 + i * 16 + (lane >> 2);
            int gcol = n0 + warp_n * 32 + j * 8 + (lane & 3) * 2;
            float b0v = bias[gcol], b1v = bias[gcol + 1];
            float v0 = c[i][j][0] + b0v;
            float v1 = c[i][j][1] + b1v;
            float v2 = c[i][j][2] + b0v;
            float v3 = c[i][j][3] + b1v;
            if (relu) {
                v0 = fmaxf(v0, 0.f); v1 = fmaxf(v1, 0.f);
                v2 = fmaxf(v2, 0.f); v3 = fmaxf(v3, 0.f);
            }
            if (mode == 0) {
                *(float2*)(Cf + (size_t)grow * N + gcol)       = make_float2(v0, v1);
                *(float2*)(Cf + (size_t)(grow + 8) * N + gcol) = make_float2(v2, v3);
            } else {
                __half2 p0 = __floats2half2_rn(v0 * qsc, v1 * qsc);
                __half2 p1 = __floats2half2_rn(v2 * qsc, v3 * qsc);
                *(__half2*)(Ch + (size_t)grow * N + gcol)       = p0;
                *(__half2*)(Ch + (size_t)(grow + 8) * N + gcol) = p1;
            }
        }
    }
}

// ---------------- tensor-core flash attention (fp16 single-pass) -------------
// Round-13 proven version: single-buffered K/V, fp32 mask direct.
#define QT 128
#define KTILE 64
#define SQ 72
#define ATTN_SMEM ((QT + 2*KTILE) * SQ * 2)    // 36864 B

__global__ void __launch_bounds__(256, 2)
attn_mma(const float* __restrict__ wm)
{
    extern __shared__ __align__(16) __half am_[];
    __half* qs = am_;                 // [row][d]
    __half* ks = qs + QT * SQ;        // [k][d]
    __half* vt = ks + KTILE * SQ;     // [d][k]

    const int tid = threadIdx.x, wid = tid >> 5, lane = tid & 31;
    const int b = blockIdx.z, h = blockIdx.y, q0 = blockIdx.x * QT;

    const uint32_t sqs = smem_u32(qs);
    const uint32_t sks = smem_u32(ks);
    const uint32_t svt = smem_u32(vt);

    // stage Q (already scaled, fp16 direct copy)
    {
        const int row = tid >> 1, cb = (tid & 1) * 32;
        const __half* src = g_qkv16 + (size_t)(b * SEQ + q0 + row) * NQKV + h * DHEAD + cb;
#pragma unroll
        for (int f = 0; f < 4; f++)
            *(uint4*)(qs + row * SQ + cb + 8 * f) = *(const uint4*)(src + 8 * f);
    }

    const int krow = tid >> 2, kcb = (tid & 3) * 16;
    uint4 rk[2], rv[2];
    {
        const __half* kp = g_qkv16 + (size_t)(b * SEQ + krow) * NQKV + HID + h * DHEAD + kcb;
        rk[0] = *(const uint4*)kp;          rk[1] = *(const uint4*)(kp + 8);
        rv[0] = *(const uint4*)(kp + HID);  rv[1] = *(const uint4*)(kp + HID + 8);
    }

    float m0 = -1e30f, m1 = -1e30f, l0 = 0.f, l1 = 0.f;
    float o[8][4];
#pragma unroll
    for (int j = 0; j < 8; j++)
#pragma unroll
        for (int r = 0; r < 4; r++) o[j][r] = 0.f;

    const int rowoff = ((lane >> 3) & 1) * 8 + (lane & 7);
    const int coloff = (lane >> 4) * 8;
    const int rA = q0 + wid * 16 + (lane >> 2);

    for (int kt = 0; kt < 16; kt++) {
        __syncthreads();
        *(uint4*)(ks + krow * SQ + kcb)     = rk[0];
        *(uint4*)(ks + krow * SQ + kcb + 8) = rk[1];
        {
            __half vv[16];
            *(uint4*)vv       = rv[0];
            *(uint4*)(vv + 8) = rv[1];
#pragma unroll
            for (int e = 0; e < 16; e++)
                vt[(kcb + e) * SQ + krow] = vv[e];
        }
        __syncthreads();
        if (kt < 15) {
            const __half* kp = g_qkv16 + (size_t)(b * SEQ + (kt + 1) * KTILE + krow) * NQKV
                               + HID + h * DHEAD + kcb;
            rk[0] = *(const uint4*)kp;          rk[1] = *(const uint4*)(kp + 8);
            rv[0] = *(const uint4*)(kp + HID);  rv[1] = *(const uint4*)(kp + HID + 8);
        }
        // mask tile (fp32, loads hidden under the QK MMAs)
        float2 mk0[8], mk1[8];
        {
            const float* mr0 = wm + ((size_t)b * SEQ + rA) * SEQ + kt * KTILE + (lane & 3) * 2;
            const float* mr1 = mr0 + 8 * SEQ;
#pragma unroll
            for (int j = 0; j < 8; j++) {
                mk0[j] = *(const float2*)(mr0 + 8 * j);
                mk1[j] = *(const float2*)(mr1 + 8 * j);
            }
        }

        float s[8][4];
#pragma unroll
        for (int j = 0; j < 8; j++)
#pragma unroll
            for (int r = 0; r < 4; r++) s[j][r] = 0.f;

#pragma unroll
        for (int t = 0; t < 4; t++) {
            uint32_t af[4];
            ldsm4(af[0], af[1], af[2], af[3],
                  sqs + ((wid * 16 + rowoff) * SQ + t * 16 + coloff) * 2);
#pragma unroll
            for (int p = 0; p < 4; p++) {
                uint32_t r0, r1, r2, r3;
                ldsm4(r0, r1, r2, r3,
                      sks + ((p * 16 + rowoff) * SQ + t * 16 + coloff) * 2);
                uint32_t b0[2] = {r0, r2}, b1[2] = {r1, r3};
                mma_f16(s[2*p],   af, b0);
                mma_f16(s[2*p+1], af, b1);
            }
        }

        float lm0 = -1e30f, lm1 = -1e30f;
#pragma unroll
        for (int j = 0; j < 8; j++) {
            lm0 = fmaxf(lm0, fmaxf(s[j][0], s[j][1]));
            lm1 = fmaxf(lm1, fmaxf(s[j][2], s[j][3]));
        }
        lm0 = fmaxf(lm0, __shfl_xor_sync(0xffffffffu, lm0, 1));
        lm0 = fmaxf(lm0, __shfl_xor_sync(0xffffffffu, lm0, 2));
        lm1 = fmaxf(lm1, __shfl_xor_sync(0xffffffffu, lm1, 1));
        lm1 = fmaxf(lm1, __shfl_xor_sync(0xffffffffu, lm1, 2));
        float mn0 = fmaxf(m0, lm0), mn1 = fmaxf(m1, lm1);
        float f0 = __expf(m0 - mn0), f1 = __expf(m1 - mn1);
        m0 = mn0; m1 = mn1;
        float ls0 = 0.f, ls1 = 0.f;
#pragma unroll
        for (int j = 0; j < 8; j++) {
            float e0 = __expf(s[j][0] - mn0);
            float e1 = __expf(s[j][1] - mn0);
            float e2 = __expf(s[j][2] - mn1);
            float e3 = __expf(s[j][3] - mn1);
            ls0 += e0 + e1; ls1 += e2 + e3;
            s[j][0] = e0 * mk0[j].x;
            s[j][1] = e1 * mk0[j].y;
            s[j][2] = e2 * mk1[j].x;
            s[j][3] = e3 * mk1[j].y;
        }
        ls0 += __shfl_xor_sync(0xffffffffu, ls0, 1);
        ls0 += __shfl_xor_sync(0xffffffffu, ls0, 2);
        ls1 += __shfl_xor_sync(0xffffffffu, ls1, 1);
        ls1 += __shfl_xor_sync(0xffffffffu, ls1, 2);
        l0 = l0 * f0 + ls0;
        l1 = l1 * f1 + ls1;
#pragma unroll
        for (int j = 0; j < 8; j++) {
            o[j][0] *= f0; o[j][1] *= f0;
            o[j][2] *= f1; o[j][3] *= f1;
        }

#pragma unroll
        for (int u = 0; u < 4; u++) {
            uint32_t pa[4];
            pa[0] = packh(s[2*u][0],   s[2*u][1]);
            pa[1] = packh(s[2*u][2],   s[2*u][3]);
            pa[2] = packh(s[2*u+1][0], s[2*u+1][1]);
            pa[3] = packh(s[2*u+1][2], s[2*u+1][3]);
#pragma unroll
            for (int p = 0; p < 4; p++) {
                uint32_t r0, r1, r2, r3;
                ldsm4(r0, r1, r2, r3,
                      svt + ((p * 16 + rowoff) * SQ + u * 16 + coloff) * 2);
                uint32_t b0[2] = {r0, r2}, b1[2] = {r1, r3};
                mma_f16(o[2*p],   pa, b0);
                mma_f16(o[2*p+1], pa, b1);
            }
        }
    }

    float inv0 = 1.0f / l0, inv1 = 1.0f / l1;
    float* c0 = g_ctx + ((size_t)(b * SEQ) + rA) * HID + h * DHEAD + (lane & 3) * 2;
    float* c1 = c0 + 8 * HID;
#pragma unroll
    for (int j = 0; j < 8; j++) {
        *(float2*)(c0 + 8 * j) = make_float2(o[j][0] * inv0, o[j][1] * inv0);
        *(float2*)(c1 + 8 * j) = make_float2(o[j][2] * inv1, o[j][3] * inv1);
    }
}

// ---------------- fused residual-add + LayerNorm -----------------------------
// ln1: residual q read from g_qkv16 fp16 (pre-scaled 1/8 -> rescale x8, exact pow2).
__global__ void __launch_bounds__(256)
ln1_kernel(const float* __restrict__ g, const float* __restrict__ be)
{
    const int row = blockIdx.x;
    const int tid = threadIdx.x;
    __shared__ float red[8];
    __shared__ float s_mu, s_rs;

    float4 v4 = make_float4(0.f, 0.f, 0.f, 0.f);
    float ls = 0.f;
    if (tid < 192) {
        float4 av = ((const float4*)(g_ctx + (size_t)row * HID))[tid];
        const __half2* qp = (const __half2*)(g_qkv16 + (size_t)row * NQKV);
        float2 q0 = __half22float2(qp[2*tid]);
        float2 q1 = __half22float2(qp[2*tid+1]);
        v4 = make_float4(av.x + 8.f*q0.x, av.y + 8.f*q0.y,
                         av.z + 8.f*q1.x, av.w + 8.f*q1.y);
        ls = v4.x + v4.y + v4.z + v4.w;
    }
    int lane = tid & 31, wid = tid >> 5;
#pragma unroll
    for (int o = 16; o; o >>= 1) ls += __shfl_xor_sync(0xffffffffu, ls, o);
    if (lane == 0) red[wid] = ls;
    __syncthreads();
    if (tid == 0) {
        float t = 0.f;
#pragma unroll
        for (int i = 0; i < 8; i++) t += red[i];
        s_mu = t * (1.0f / HID);
    }
    __syncthreads();
    float mu = s_mu;

    float4 dx = make_float4(v4.x - mu, v4.y - mu, v4.z - mu, v4.w - mu);
    float lv = 0.f;
    if (tid < 192)
        lv = dx.x * dx.x + dx.y * dx.y + dx.z * dx.z + dx.w * dx.w;
#pragma unroll
    for (int o = 16; o; o >>= 1) lv += __shfl_xor_sync(0xffffffffu, lv, o);
    __syncthreads();
    if (lane == 0) red[wid] = lv;
    __syncthreads();
    if (tid == 0) {
        float t = 0.f;
#pragma unroll
        for (int i = 0; i < 8; i++) t += red[i];
        s_rs = rsqrtf(t * (1.0f / HID) + 1e-5f);
    }
    __syncthreads();
    float rs = s_rs;

    if (tid < 192) {
        float4 g4  = ((const float4*)g)[tid];
        float4 be4 = ((const float4*)be)[tid];
        float4 o = make_float4(dx.x * rs * g4.x + be4.x,
                               dx.y * rs * g4.y + be4.y,
                               dx.z * rs * g4.z + be4.z,
                               dx.w * rs * g4.w + be4.w);
        ((float4*)(g_x + (size_t)row * HID))[tid] = o;
        ((__half2*)(g_ah + (size_t)row * HID))[2*tid]   = __floats2half2_rn(o.x, o.y);
        ((__half2*)(g_ah + (size_t)row * HID))[2*tid+1] = __floats2half2_rn(o.z, o.w);
    }
}

__global__ void __launch_bounds__(256)
ln2_kernel(const float* __restrict__ g, const float* __restrict__ be,
           float* __restrict__ out)
{
    const int row = blockIdx.x;
    const int tid = threadIdx.x;
    __shared__ float red[8];
    __shared__ float s_mu, s_rs;

    float4 v4 = make_float4(0.f, 0.f, 0.f, 0.f);
    float ls = 0.f;
    if (tid < 192) {
        float4 av = ((const float4*)(g_x   + (size_t)row * HID))[tid];
        float4 bv = ((const float4*)(g_ff2 + (size_t)row * HID))[tid];
        v4 = make_float4(av.x + bv.x, av.y + bv.y, av.z + bv.z, av.w + bv.w);
        ls = v4.x + v4.y + v4.z + v4.w;
    }
    int lane = tid & 31, wid = tid >> 5;
#pragma unroll
    for (int o = 16; o; o >>= 1) ls += __shfl_xor_sync(0xffffffffu, ls, o);
    if (lane == 0) red[wid] = ls;
    __syncthreads();
    if (tid == 0) {
        float t = 0.f;
#pragma unroll
        for (int i = 0; i < 8; i++) t += red[i];
        s_mu = t * (1.0f / HID);
    }
    __syncthreads();
    float mu = s_mu;

    float4 dx = make_float4(v4.x - mu, v4.y - mu, v4.z - mu, v4.w - mu);
    float lv = 0.f;
    if (tid < 192)
        lv = dx.x * dx.x + dx.y * dx.y + dx.z * dx.z + dx.w * dx.w;
#pragma unroll
    for (int o = 16; o; o >>= 1) lv += __shfl_xor_sync(0xffffffffu, lv, o);
    __syncthreads();
    if (lane == 0) red[wid] = lv;
    __syncthreads();
    if (tid == 0) {
        float t = 0.f;
#pragma unroll
        for (int i = 0; i < 8; i++) t += red[i];
        s_rs = rsqrtf(t * (1.0f / HID) + 1e-5f);
    }
    __syncthreads();
    float rs = s_rs;

    if (tid < 192) {
        float4 g4  = ((const float4*)g)[tid];
        float4 be4 = ((const float4*)be)[tid];
        float4 o = make_float4(dx.x * rs * g4.x + be4.x,
                               dx.y * rs * g4.y + be4.y,
                               dx.z * rs * g4.z + be4.z,
                               dx.w * rs * g4.w + be4.w);
        ((float4*)(out + (size_t)row * HID))[tid] = o;
    }
}

// ---------------- launch -----------------------------------------------------
extern "C" void kernel_launch(void* const* d_in, const int* in_sizes, int n_in,
                              void* d_out, int out_size)
{
    const float* x1  = (const float*)d_in[0];
    const float* wm  = (const float*)d_in[1];
    const float* Wq  = (const float*)d_in[2];
    const float* bq  = (const float*)d_in[3];
    const float* Wk  = (const float*)d_in[4];
    const float* bk  = (const float*)d_in[5];
    const float* Wv  = (const float*)d_in[6];
    const float* bv  = (const float*)d_in[7];
    const float* g1  = (const float*)d_in[8];
    const float* be1 = (const float*)d_in[9];
    const float* g2  = (const float*)d_in[10];
    const float* be2 = (const float*)d_in[11];
    const float* W1  = (const float*)d_in[12];
    const float* b1  = (const float*)d_in[13];
    const float* W2  = (const float*)d_in[14];
    const float* b2  = (const float*)d_in[15];
    float* out = (float*)d_out;

    void *p_ah, *p_fh, *p_w1h, *p_w2h;
    void *p_qkv16, *p_bqkv, *p_ff2, *p_wqh;
    cudaGetSymbolAddress(&p_ah, g_ah);
    cudaGetSymbolAddress(&p_fh, g_fh);
    cudaGetSymbolAddress(&p_w1h, g_w1h);
    cudaGetSymbolAddress(&p_w2h, g_w2h);
    cudaGetSymbolAddress(&p_qkv16, g_qkv16);
    cudaGetSymbolAddress(&p_bqkv, g_bqkv);
    cudaGetSymbolAddress(&p_ff2, g_ff2);
    cudaGetSymbolAddress(&p_wqh, g_wqkvh);

    __half* ah    = (__half*)p_ah;
    __half* fh    = (__half*)p_fh;
    __half* wqh   = (__half*)p_wqh;
    __half* w1h   = (__half*)p_w1h;
    __half* w2h   = (__half*)p_w2h;
    __half* qkv16 = (__half*)p_qkv16;
    float* bqkv   = (float*)p_bqkv;
    float* ff2    = (float*)p_ff2;

    cudaFuncSetAttribute(attn_mma,
                         cudaFuncAttributeMaxDynamicSharedMemorySize, ATTN_SMEM);
    cudaFuncSetAttribute(gemm_mma,
                         cudaFuncAttributeMaxDynamicSharedMemorySize, GEMM_SMEM);

    // 1: fused prep (weight transposes + bias + x1 convert) in ONE launch
    prep_all<<<NB_PREP, 256>>>(x1, Wq, Wk, Wv, W1, W2, bq, bk, bv);

    // 2: fused QKV GEMM: fp16 out, q pre-scaled 1/8 (mode 2)
    gemm_mma<<<dim3(NQKV/128, ROWS/128), 256, GEMM_SMEM>>>(
        ah, wqh, bqkv, nullptr, qkv16, NQKV, HID, 0, 2);

    // 3: fp16 flash attention with post-softmax mask (fp32 mask direct)
    attn_mma<<<dim3(SEQ/QT, NHEAD, BATCH), 256, ATTN_SMEM>>>(wm);

    // 4: x = LN(ctx + q_mixed), q reconstructed from fp16 (x8), fused fp16 emit
    ln1_kernel<<<ROWS, 256>>>(g1, be1);

    // 5: ff1 = relu(x @ W1 + b1) -> fp16
    gemm_mma<<<dim3(FF/128, ROWS/128), 256, GEMM_SMEM>>>(
        ah, w1h, b1, nullptr, fh, FF, HID, 1, 1);

    // 6: ff2 = ff1 @ W2 + b2 -> fp32
    gemm_mma<<<dim3(HID/128, ROWS/128), 256, GEMM_SMEM>>>(
        fh, w2h, b2, ff2, nullptr, HID, FF, 0, 0);

    // 7: out = LN(x + ff2)
    ln2_kernel<<<ROWS, 256>>>(g2, be2, out);
}

// round 16
// speedup vs baseline: 1.0171x; 1.0002x over previous
#include <cuda_runtime.h>
#include <cuda_bf16.h>
#include <cuda_fp16.h>
#include <cstdint>
#include <math.h>

// Problem constants
#define BATCH 8
#define SEQ   1024
#define HID   768
#define NHEAD 12
#define DHEAD 64
#define ROWS  (BATCH*SEQ)          // 8192
#define FF    (2*HID)              // 1536
#define NQKV  (3*HID)              // 2304

// ---------------- scratch (device globals; no allocations allowed) ----------
__device__ float g_ctx[ROWS*HID];
__device__ float g_x  [ROWS*HID];
__device__ float g_ff2[ROWS*HID];
__device__ float g_bqkv[NQKV];

__device__ __half g_qkv16[ROWS*NQKV];  // q(pre-scaled 1/8) | k | v, fp16
__device__ __half g_ah[ROWS*HID];      // fp16 activations (A inputs)
__device__ __half g_fh[ROWS*FF];       // fp16 ff1 output (A for ff2)
__device__ __half g_wqkvh[NQKV*HID];   // W^T fp16, rows = N, K-major
__device__ __half g_w1h[FF*HID];
__device__ __half g_w2h[HID*FF];

// ---------------- PTX helpers (sm_80-era only; no 'a'-features) -------------
__device__ __forceinline__ uint32_t smem_u32(const void* p) {
    uint32_t a;
    asm("{ .reg .u64 t; cvta.to.shared.u64 t, %1; cvt.u32.u64 %0, t; }"
        : "=r"(a) : "l"(p));
    return a;
}

__device__ __forceinline__ void cp16(uint32_t dst, const void* src) {
    asm volatile("cp.async.cg.shared.global [%0], [%1], 16;"
                 :: "r"(dst), "l"(src));
}
#define CP_COMMIT() asm volatile("cp.async.commit_group;" ::: "memory")
#define CP_WAIT(n)  asm volatile("cp.async.wait_group %0;" :: "n"(n) : "memory")

__device__ __forceinline__ void ldsm4(uint32_t& r0, uint32_t& r1,
                                      uint32_t& r2, uint32_t& r3, uint32_t addr) {
    asm volatile("ldmatrix.sync.aligned.m8n8.x4.shared.b16 {%0,%1,%2,%3}, [%4];"
                 : "=r"(r0), "=r"(r1), "=r"(r2), "=r"(r3) : "r"(addr));
}

__device__ __forceinline__ void mma_f16(float* c, const uint32_t* a, const uint32_t* b) {
    asm volatile("mma.sync.aligned.m16n8k16.row.col.f32.f16.f16.f32 "
                 "{%0,%1,%2,%3}, {%4,%5,%6,%7}, {%8,%9}, {%0,%1,%2,%3};"
                 : "+f"(c[0]), "+f"(c[1]), "+f"(c[2]), "+f"(c[3])
                 : "r"(a[0]), "r"(a[1]), "r"(a[2]), "r"(a[3]),
                   "r"(b[0]), "r"(b[1]));
}

__device__ __forceinline__ uint32_t packh(float x, float y) {
    __half2 p = __floats2half2_rn(x, y);
    return *(uint32_t*)&p;
}

// ---------------- fused prep kernel ------------------------------------------
#define NB_QKV  1728                        // 3 * 24 * 24
#define NB_W1   1152                        // 48 * 24
#define NB_W2   1152                        // 24 * 48
#define NB_BIAS 3
#define NB_CVT  2048
#define NB_PREP (NB_QKV + NB_W1 + NB_W2 + NB_BIAS + NB_CVT)  // 6083

__device__ __forceinline__ void tsp_tile(const float* __restrict__ W,
                                         __half* __restrict__ oh,
                                         int K, int N, int n0, int k0) {
    __shared__ float t[32][33];
    const int tx = threadIdx.x & 31, ty = threadIdx.x >> 5;
#pragma unroll
    for (int i = 0; i < 4; i++)
        t[ty + 8*i][tx] = W[(size_t)(k0 + ty + 8*i) * N + n0 + tx];
    __syncthreads();
#pragma unroll
    for (int i = 0; i < 4; i++) {
        float v = t[tx][ty + 8*i];
        oh[(size_t)(n0 + ty + 8*i) * K + k0 + tx] = __float2half_rn(v);
    }
}

__global__ void __launch_bounds__(256)
prep_all(const float* __restrict__ x1,
         const float* __restrict__ Wq, const float* __restrict__ Wk,
         const float* __restrict__ Wv,
         const float* __restrict__ W1, const float* __restrict__ W2,
         const float* __restrict__ bq, const float* __restrict__ bk,
         const float* __restrict__ bv)
{
    const int bid = blockIdx.x;
    const int tid = threadIdx.x;

    if (bid < NB_QKV) {
        const int z = bid / 576, r = bid % 576;
        const int n0 = (r % 24) * 32, k0 = (r / 24) * 32;
        const float* W = (z == 0) ? Wq : (z == 1) ? Wk : Wv;
        tsp_tile(W, g_wqkvh + (size_t)z * HID * HID, HID, HID, n0, k0);
    } else if (bid < NB_QKV + NB_W1) {
        const int r = bid - NB_QKV;
        const int n0 = (r % 48) * 32, k0 = (r / 48) * 32;   // N=FF, K=HID
        tsp_tile(W1, g_w1h, HID, FF, n0, k0);
    } else if (bid < NB_QKV + NB_W1 + NB_W2) {
        const int r = bid - (NB_QKV + NB_W1);
        const int n0 = (r % 24) * 32, k0 = (r / 24) * 32;   // N=HID, K=FF
        tsp_tile(W2, g_w2h, FF, HID, n0, k0);
    } else if (bid < NB_QKV + NB_W1 + NB_W2 + NB_BIAS) {
        const int i = (bid - (NB_QKV + NB_W1 + NB_W2)) * 256 + tid;
        if (i < HID) {
            g_bqkv[i]         = bq[i];
            g_bqkv[i + HID]   = bk[i];
            g_bqkv[i + 2*HID] = bv[i];
        }
    } else {
        const int cb = bid - (NB_QKV + NB_W1 + NB_W2 + NB_BIAS);
        const int n4 = ROWS * HID / 4;
        for (int i = cb * 256 + tid; i < n4; i += NB_CVT * 256) {
            float4 a = ((const float4*)x1)[i];
            ((__half2*)g_ah)[2*i]   = __floats2half2_rn(a.x, a.y);
            ((__half2*)g_ah)[2*i+1] = __floats2half2_rn(a.z, a.w);
        }
    }
}

// ---------------- fp16 single-pass mma.sync GEMM (128x128, 4-stage, occ 2) ---
// mode 0: fp32 out. mode 1: fp16 out. mode 2 (QKV): fp16 out, q cols scaled 1/8.
#define ASTR    40
#define STGB    (128 * ASTR * 2)
#define STAGES  4
#define GEMM_SMEM (STAGES * 2 * STGB)        // 81920 B

__global__ void __launch_bounds__(256, 2)
gemm_mma(const __half* __restrict__ A, const __half* __restrict__ B,
         const float* __restrict__ bias,
         float* __restrict__ Cf, __half* __restrict__ Ch,
         int N, int K, int relu, int mode)
{
    extern __shared__ __align__(16) char dsm[];
    __half* smA = (__half*)dsm;
    __half* smB = (__half*)(dsm + STAGES * STGB);

    const int tid  = threadIdx.x;
    const int wid  = tid >> 5, lane = tid & 31;
    const int warp_m = wid >> 2;
    const int warp_n = wid & 3;
    const int m0 = blockIdx.y << 7;
    const int n0 = blockIdx.x << 7;

    const uint32_t sA = smem_u32(smA);
    const uint32_t sB = smem_u32(smB);

    const int lrow  = tid >> 1;
    const int lcolh = (tid & 1) * 16;

    const int kb = K >> 5;

    float c[4][4][4];
#pragma unroll
    for (int i = 0; i < 4; i++)
#pragma unroll
        for (int j = 0; j < 4; j++)
#pragma unroll
            for (int r = 0; r < 4; r++) c[i][j][r] = 0.f;

    const int rowoff = ((lane >> 3) & 1) * 8 + (lane & 7);
    const int coloff = ((lane >> 4) & 1) * 8;

    auto issue = [&](int blk) {
        if (blk < kb) {
            const __half* ga = A + (size_t)(m0 + lrow) * K + blk * 32 + lcolh;
            const __half* gb = B + (size_t)(n0 + lrow) * K + blk * 32 + lcolh;
            int st = blk & (STAGES - 1);
            uint32_t da = sA + st * STGB + (lrow * ASTR + lcolh) * 2;
            uint32_t db = sB + st * STGB + (lrow * ASTR + lcolh) * 2;
            cp16(da,      ga);
            cp16(da + 16, ga + 8);
            cp16(db,      gb);
            cp16(db + 16, gb + 8);
        }
        CP_COMMIT();
    };

    issue(0); issue(1); issue(2);

    for (int blk = 0; blk < kb; blk++) {
        CP_WAIT(2);
        __syncthreads();

        const int stage = blk & (STAGES - 1);
        const uint32_t a0 = sA + stage * STGB;
        const uint32_t b0 = sB + stage * STGB;
#pragma unroll
        for (int kh = 0; kh < 2; kh++) {
            uint32_t af[4][4];
#pragma unroll
            for (int t = 0; t < 4; t++)
                ldsm4(af[t][0], af[t][1], af[t][2], af[t][3],
                      a0 + ((warp_m * 64 + t * 16 + rowoff) * ASTR + kh * 16 + coloff) * 2);
            uint32_t bf[4][2];
#pragma unroll
            for (int p = 0; p < 2; p++) {
                uint32_t r0, r1, r2, r3;
                ldsm4(r0, r1, r2, r3,
                      b0 + ((warp_n * 32 + p * 16 + rowoff) * ASTR + kh * 16 + coloff) * 2);
                bf[2*p][0]   = r0; bf[2*p][1]   = r2;
                bf[2*p+1][0] = r1; bf[2*p+1][1] = r3;
            }
#pragma unroll
            for (int i = 0; i < 4; i++)
#pragma unroll
                for (int j = 0; j < 4; j++)
                    mma_f16(c[i][j], af[i], bf[j]);
        }
        issue(blk + 3);
    }

    const float qsc = (mode == 2 && n0 < HID) ? 0.125f : 1.0f;

#pragma unroll
    for (int i = 0; i < 4; i++) {
#pragma unroll
        for (int j = 0; j < 4; j++) {
            int grow = m0 + warp_m * 64 + i * 16 + (lane >> 2);
            int gcol = n0 + warp_n * 32 + j * 8 + (lane & 3) * 2;
            float b0v = bias[gcol], b1v = bias[gcol + 1];
            float v0 = c[i][j][0] + b0v;
            float v1 = c[i][j][1] + b1v;
            float v2 = c[i][j][2] + b0v;
            float v3 = c[i][j][3] + b1v;
            if (relu) {
                v0 = fmaxf(v0, 0.f); v1 = fmaxf(v1, 0.f);
                v2 = fmaxf(v2, 0.f); v3 = fmaxf(v3, 0.f);
            }
            if (mode == 0) {
                *(float2*)(Cf + (size_t)grow * N + gcol)       = make_float2(v0, v1);
                *(float2*)(Cf + (size_t)(grow + 8) * N + gcol) = make_float2(v2, v3);
            } else {
                __half2 p0 = __floats2half2_rn(v0 * qsc, v1 * qsc);
                __half2 p1 = __floats2half2_rn(v2 * qsc, v3 * qsc);
                *(__half2*)(Ch + (size_t)grow * N + gcol)       = p0;
                *(__half2*)(Ch + (size_t)(grow + 8) * N + gcol) = p1;
            }
        }
    }
}

// ---------------- tensor-core flash attention (fp16 single-pass) -------------
// Grid: x = head, y = q-tile, z = batch -> concurrent CTAs share (b, q-tile)
// and differ in head, so the (head-independent) mask tiles hit L2.
#define QT 128
#define KTILE 64
#define SQ 72
#define ATTN_SMEM ((QT + 2*KTILE) * SQ * 2)    // 36864 B

__global__ void __launch_bounds__(256, 2)
attn_mma(const float* __restrict__ wm)
{
    extern __shared__ __align__(16) __half am_[];
    __half* qs = am_;                 // [row][d]
    __half* ks = qs + QT * SQ;        // [k][d]
    __half* vt = ks + KTILE * SQ;     // [d][k]

    const int tid = threadIdx.x, wid = tid >> 5, lane = tid & 31;
    const int h = blockIdx.x, b = blockIdx.z, q0 = blockIdx.y * QT;

    const uint32_t sqs = smem_u32(qs);
    const uint32_t sks = smem_u32(ks);
    const uint32_t svt = smem_u32(vt);

    // stage Q (already scaled, fp16 direct copy)
    {
        const int row = tid >> 1, cb = (tid & 1) * 32;
        const __half* src = g_qkv16 + (size_t)(b * SEQ + q0 + row) * NQKV + h * DHEAD + cb;
#pragma unroll
        for (int f = 0; f < 4; f++)
            *(uint4*)(qs + row * SQ + cb + 8 * f) = *(const uint4*)(src + 8 * f);
    }

    const int krow = tid >> 2, kcb = (tid & 3) * 16;
    uint4 rk[2], rv[2];
    {
        const __half* kp = g_qkv16 + (size_t)(b * SEQ + krow) * NQKV + HID + h * DHEAD + kcb;
        rk[0] = *(const uint4*)kp;          rk[1] = *(const uint4*)(kp + 8);
        rv[0] = *(const uint4*)(kp + HID);  rv[1] = *(const uint4*)(kp + HID + 8);
    }

    float m0 = -1e30f, m1 = -1e30f, l0 = 0.f, l1 = 0.f;
    float o[8][4];
#pragma unroll
    for (int j = 0; j < 8; j++)
#pragma unroll
        for (int r = 0; r < 4; r++) o[j][r] = 0.f;

    const int rowoff = ((lane >> 3) & 1) * 8 + (lane & 7);
    const int coloff = (lane >> 4) * 8;
    const int rA = q0 + wid * 16 + (lane >> 2);

    for (int kt = 0; kt < 16; kt++) {
        __syncthreads();
        *(uint4*)(ks + krow * SQ + kcb)     = rk[0];
        *(uint4*)(ks + krow * SQ + kcb + 8) = rk[1];
        {
            __half vv[16];
            *(uint4*)vv       = rv[0];
            *(uint4*)(vv + 8) = rv[1];
#pragma unroll
            for (int e = 0; e < 16; e++)
                vt[(kcb + e) * SQ + krow] = vv[e];
        }
        __syncthreads();
        if (kt < 15) {
            const __half* kp = g_qkv16 + (size_t)(b * SEQ + (kt + 1) * KTILE + krow) * NQKV
                               + HID + h * DHEAD + kcb;
            rk[0] = *(const uint4*)kp;          rk[1] = *(const uint4*)(kp + 8);
            rv[0] = *(const uint4*)(kp + HID);  rv[1] = *(const uint4*)(kp + HID + 8);
        }
        // mask tile (fp32, hidden under the QK MMAs; L2-shared across heads)
        float2 mk0[8], mk1[8];
        {
            const float* mr0 = wm + ((size_t)b * SEQ + rA) * SEQ + kt * KTILE + (lane & 3) * 2;
            const float* mr1 = mr0 + 8 * SEQ;
#pragma unroll
            for (int j = 0; j < 8; j++) {
                mk0[j] = *(const float2*)(mr0 + 8 * j);
                mk1[j] = *(const float2*)(mr1 + 8 * j);
            }
        }

        float s[8][4];
#pragma unroll
        for (int j = 0; j < 8; j++)
#pragma unroll
            for (int r = 0; r < 4; r++) s[j][r] = 0.f;

#pragma unroll
        for (int t = 0; t < 4; t++) {
            uint32_t af[4];
            ldsm4(af[0], af[1], af[2], af[3],
                  sqs + ((wid * 16 + rowoff) * SQ + t * 16 + coloff) * 2);
#pragma unroll
            for (int p = 0; p < 4; p++) {
                uint32_t r0, r1, r2, r3;
                ldsm4(r0, r1, r2, r3,
                      sks + ((p * 16 + rowoff) * SQ + t * 16 + coloff) * 2);
                uint32_t b0[2] = {r0, r2}, b1[2] = {r1, r3};
                mma_f16(s[2*p],   af, b0);
                mma_f16(s[2*p+1], af, b1);
            }
        }

        float lm0 = -1e30f, lm1 = -1e30f;
#pragma unroll
        for (int j = 0; j < 8; j++) {
            lm0 = fmaxf(lm0, fmaxf(s[j][0], s[j][1]));
            lm1 = fmaxf(lm1, fmaxf(s[j][2], s[j][3]));
        }
        lm0 = fmaxf(lm0, __shfl_xor_sync(0xffffffffu, lm0, 1));
        lm0 = fmaxf(lm0, __shfl_xor_sync(0xffffffffu, lm0, 2));
        lm1 = fmaxf(lm1, __shfl_xor_sync(0xffffffffu, lm1, 1));
        lm1 = fmaxf(lm1, __shfl_xor_sync(0xffffffffu, lm1, 2));
        float mn0 = fmaxf(m0, lm0), mn1 = fmaxf(m1, lm1);
        float f0 = __expf(m0 - mn0), f1 = __expf(m1 - mn1);
        m0 = mn0; m1 = mn1;
        float ls0 = 0.f, ls1 = 0.f;
#pragma unroll
        for (int j = 0; j < 8; j++) {
            float e0 = __expf(s[j][0] - mn0);
            float e1 = __expf(s[j][1] - mn0);
            float e2 = __expf(s[j][2] - mn1);
            float e3 = __expf(s[j][3] - mn1);
            ls0 += e0 + e1; ls1 += e2 + e3;
            s[j][0] = e0 * mk0[j].x;
            s[j][1] = e1 * mk0[j].y;
            s[j][2] = e2 * mk1[j].x;
            s[j][3] = e3 * mk1[j].y;
        }
        ls0 += __shfl_xor_sync(0xffffffffu, ls0, 1);
        ls0 += __shfl_xor_sync(0xffffffffu, ls0, 2);
        ls1 += __shfl_xor_sync(0xffffffffu, ls1, 1);
        ls1 += __shfl_xor_sync(0xffffffffu, ls1, 2);
        l0 = l0 * f0 + ls0;
        l1 = l1 * f1 + ls1;
#pragma unroll
        for (int j = 0; j < 8; j++) {
            o[j][0] *= f0; o[j][1] *= f0;
            o[j][2] *= f1; o[j][3] *= f1;
        }

#pragma unroll
        for (int u = 0; u < 4; u++) {
            uint32_t pa[4];
            pa[0] = packh(s[2*u][0],   s[2*u][1]);
            pa[1] = packh(s[2*u][2],   s[2*u][3]);
            pa[2] = packh(s[2*u+1][0], s[2*u+1][1]);
            pa[3] = packh(s[2*u+1][2], s[2*u+1][3]);
#pragma unroll
            for (int p = 0; p < 4; p++) {
                uint32_t r0, r1, r2, r3;
                ldsm4(r0, r1, r2, r3,
                      svt + ((p * 16 + rowoff) * SQ + u * 16 + coloff) * 2);
                uint32_t b0[2] = {r0, r2}, b1[2] = {r1, r3};
                mma_f16(o[2*p],   pa, b0);
                mma_f16(o[2*p+1], pa, b1);
            }
        }
    }

    float inv0 = 1.0f / l0, inv1 = 1.0f / l1;
    float* c0 = g_ctx + ((size_t)(b * SEQ) + rA) * HID + h * DHEAD + (lane & 3) * 2;
    float* c1 = c0 + 8 * HID;
#pragma unroll
    for (int j = 0; j < 8; j++) {
        *(float2*)(c0 + 8 * j) = make_float2(o[j][0] * inv0, o[j][1] * inv0);
        *(float2*)(c1 + 8 * j) = make_float2(o[j][2] * inv1, o[j][3] * inv1);
    }
}

// ---------------- fused residual-add + LayerNorm (one-pass sum/sumsq) --------
// ln1: residual q read from g_qkv16 fp16 (pre-scaled 1/8 -> rescale x8, exact pow2).
__global__ void __launch_bounds__(256)
ln1_kernel(const float* __restrict__ g, const float* __restrict__ be)
{
    const int row = blockIdx.x;
    const int tid = threadIdx.x;
    __shared__ float redS[8], redQ[8];
    __shared__ float s_mu, s_rs;

    float4 v4 = make_float4(0.f, 0.f, 0.f, 0.f);
    float ls = 0.f, lq = 0.f;
    if (tid < 192) {
        float4 av = ((const float4*)(g_ctx + (size_t)row * HID))[tid];
        const __half2* qp = (const __half2*)(g_qkv16 + (size_t)row * NQKV);
        float2 q0 = __half22float2(qp[2*tid]);
        float2 q1 = __half22float2(qp[2*tid+1]);
        v4 = make_float4(av.x + 8.f*q0.x, av.y + 8.f*q0.y,
                         av.z + 8.f*q1.x, av.w + 8.f*q1.y);
        ls = v4.x + v4.y + v4.z + v4.w;
        lq = v4.x*v4.x + v4.y*v4.y + v4.z*v4.z + v4.w*v4.w;
    }
    int lane = tid & 31, wid = tid >> 5;
#pragma unroll
    for (int o = 16; o; o >>= 1) {
        ls += __shfl_xor_sync(0xffffffffu, ls, o);
        lq += __shfl_xor_sync(0xffffffffu, lq, o);
    }
    if (lane == 0) { redS[wid] = ls; redQ[wid] = lq; }
    __syncthreads();
    if (tid == 0) {
        float ts = 0.f, tq = 0.f;
#pragma unroll
        for (int i = 0; i < 8; i++) { ts += redS[i]; tq += redQ[i]; }
        float mu = ts * (1.0f / HID);
        s_mu = mu;
        s_rs = rsqrtf(tq * (1.0f / HID) - mu * mu + 1e-5f);
    }
    __syncthreads();
    float mu = s_mu, rs = s_rs;

    if (tid < 192) {
        float4 g4  = ((const float4*)g)[tid];
        float4 be4 = ((const float4*)be)[tid];
        float4 o = make_float4((v4.x - mu) * rs * g4.x + be4.x,
                               (v4.y - mu) * rs * g4.y + be4.y,
                               (v4.z - mu) * rs * g4.z + be4.z,
                               (v4.w - mu) * rs * g4.w + be4.w);
        ((float4*)(g_x + (size_t)row * HID))[tid] = o;
        ((__half2*)(g_ah + (size_t)row * HID))[2*tid]   = __floats2half2_rn(o.x, o.y);
        ((__half2*)(g_ah + (size_t)row * HID))[2*tid+1] = __floats2half2_rn(o.z, o.w);
    }
}

__global__ void __launch_bounds__(256)
ln2_kernel(const float* __restrict__ g, const float* __restrict__ be,
           float* __restrict__ out)
{
    const int row = blockIdx.x;
    const int tid = threadIdx.x;
    __shared__ float redS[8], redQ[8];
    __shared__ float s_mu, s_rs;

    float4 v4 = make_float4(0.f, 0.f, 0.f, 0.f);
    float ls = 0.f, lq = 0.f;
    if (tid < 192) {
        float4 av = ((const float4*)(g_x   + (size_t)row * HID))[tid];
        float4 bv = ((const float4*)(g_ff2 + (size_t)row * HID))[tid];
        v4 = make_float4(av.x + bv.x, av.y + bv.y, av.z + bv.z, av.w + bv.w);
        ls = v4.x + v4.y + v4.z + v4.w;
        lq = v4.x*v4.x + v4.y*v4.y + v4.z*v4.z + v4.w*v4.w;
    }
    int lane = tid & 31, wid = tid >> 5;
#pragma unroll
    for (int o = 16; o; o >>= 1) {
        ls += __shfl_xor_sync(0xffffffffu, ls, o);
        lq += __shfl_xor_sync(0xffffffffu, lq, o);
    }
    if (lane == 0) { redS[wid] = ls; redQ[wid] = lq; }
    __syncthreads();
    if (tid == 0) {
        float ts = 0.f, tq = 0.f;
#pragma unroll
        for (int i = 0; i < 8; i++) { ts += redS[i]; tq += redQ[i]; }
        float mu = ts * (1.0f / HID);
        s_mu = mu;
        s_rs = rsqrtf(tq * (1.0f / HID) - mu * mu + 1e-5f);
    }
    __syncthreads();
    float mu = s_mu, rs = s_rs;

    if (tid < 192) {
        float4 g4  = ((const float4*)g)[tid];
        float4 be4 = ((const float4*)be)[tid];
        float4 o = make_float4((v4.x - mu) * rs * g4.x + be4.x,
                               (v4.y - mu) * rs * g4.y + be4.y,
                               (v4.z - mu) * rs * g4.z + be4.z,
                               (v4.w - mu) * rs * g4.w + be4.w);
        ((float4*)(out + (size_t)row * HID))[tid] = o;
    }
}

// ---------------- launch -----------------------------------------------------
extern "C" void kernel_launch(void* const* d_in, const int* in_sizes, int n_in,
                              void* d_out, int out_size)
{
    const float* x1  = (const float*)d_in[0];
    const float* wm  = (const float*)d_in[1];
    const float* Wq  = (const float*)d_in[2];
    const float* bq  = (const float*)d_in[3];
    const float* Wk  = (const float*)d_in[4];
    const float* bk  = (const float*)d_in[5];
    const float* Wv  = (const float*)d_in[6];
    const float* bv  = (const float*)d_in[7];
    const float* g1  = (const float*)d_in[8];
    const float* be1 = (const float*)d_in[9];
    const float* g2  = (const float*)d_in[10];
    const float* be2 = (const float*)d_in[11];
    const float* W1  = (const float*)d_in[12];
    const float* b1  = (const float*)d_in[13];
    const float* W2  = (const float*)d_in[14];
    const float* b2  = (const float*)d_in[15];
    float* out = (float*)d_out;

    void *p_ah, *p_fh, *p_w1h, *p_w2h;
    void *p_qkv16, *p_bqkv, *p_ff2, *p_wqh;
    cudaGetSymbolAddress(&p_ah, g_ah);
    cudaGetSymbolAddress(&p_fh, g_fh);
    cudaGetSymbolAddress(&p_w1h, g_w1h);
    cudaGetSymbolAddress(&p_w2h, g_w2h);
    cudaGetSymbolAddress(&p_qkv16, g_qkv16);
    cudaGetSymbolAddress(&p_bqkv, g_bqkv);
    cudaGetSymbolAddress(&p_ff2, g_ff2);
    cudaGetSymbolAddress(&p_wqh, g_wqkvh);

    __half* ah    = (__half*)p_ah;
    __half* fh    = (__half*)p_fh;
    __half* wqh   = (__half*)p_wqh;
    __half* w1h   = (__half*)p_w1h;
    __half* w2h   = (__half*)p_w2h;
    __half* qkv16 = (__half*)p_qkv16;
    float* bqkv   = (float*)p_bqkv;
    float* ff2    = (float*)p_ff2;

    cudaFuncSetAttribute(attn_mma,
                         cudaFuncAttributeMaxDynamicSharedMemorySize, ATTN_SMEM);
    cudaFuncSetAttribute(gemm_mma,
                         cudaFuncAttributeMaxDynamicSharedMemorySize, GEMM_SMEM);

    // 1: fused prep (weight transposes + bias + x1 convert) in ONE launch
    prep_all<<<NB_PREP, 256>>>(x1, Wq, Wk, Wv, W1, W2, bq, bk, bv);

    // 2: fused QKV GEMM: fp16 out, q pre-scaled 1/8 (mode 2)
    gemm_mma<<<dim3(NQKV/128, ROWS/128), 256, GEMM_SMEM>>>(
        ah, wqh, bqkv, nullptr, qkv16, NQKV, HID, 0, 2);

    // 3: fp16 flash attention; grid x=head so mask tiles hit L2 across heads
    attn_mma<<<dim3(NHEAD, SEQ/QT, BATCH), 256, ATTN_SMEM>>>(wm);

    // 4: x = LN(ctx + q_mixed), one-pass reduction, fused fp16 emit
    ln1_kernel<<<ROWS, 256>>>(g1, be1);

    // 5: ff1 = relu(x @ W1 + b1) -> fp16
    gemm_mma<<<dim3(FF/128, ROWS/128), 256, GEMM_SMEM>>>(
        ah, w1h, b1, nullptr, fh, FF, HID, 1, 1);

    // 6: ff2 = ff1 @ W2 + b2 -> fp32
    gemm_mma<<<dim3(HID/128, ROWS/128), 256, GEMM_SMEM>>>(
        fh, w2h, b2, ff2, nullptr, HID, FF, 0, 0);

    // 7: out = LN(x + ff2)
    ln2_kernel<<<ROWS, 256>>>(g2, be2, out);
}

// round 17
// speedup vs baseline: 1.0246x; 1.0074x over previous
#include <cuda_runtime.h>
#include <cuda_bf16.h>
#include <cuda_fp16.h>
#include <cstdint>
#include <math.h>

// Problem constants
#define BATCH 8
#define SEQ   1024
#define HID   768
#define NHEAD 12
#define DHEAD 64
#define ROWS  (BATCH*SEQ)          // 8192
#define FF    (2*HID)              // 1536
#define NQKV  (3*HID)              // 2304

// ---------------- scratch (device globals; no allocations allowed) ----------
__device__ float g_x  [ROWS*HID];
__device__ float g_ff2[ROWS*HID];      // after ff2: holds x + ff2 (fused add)
__device__ float g_bqkv[NQKV];

__device__ __half g_ctx16[ROWS*HID];   // attention output, fp16
__device__ __half g_qkv16[ROWS*NQKV];  // q(pre-scaled 1/8) | k | v, fp16
__device__ __half g_ah[ROWS*HID];      // fp16 activations (A inputs)
__device__ __half g_fh[ROWS*FF];       // fp16 ff1 output (A for ff2)
__device__ __half g_wqkvh[NQKV*HID];   // W^T fp16, rows = N, K-major
__device__ __half g_w1h[FF*HID];
__device__ __half g_w2h[HID*FF];

// ---------------- PTX helpers (sm_80-era only; no 'a'-features) -------------
__device__ __forceinline__ uint32_t smem_u32(const void* p) {
    uint32_t a;
    asm("{ .reg .u64 t; cvta.to.shared.u64 t, %1; cvt.u32.u64 %0, t; }"
        : "=r"(a) : "l"(p));
    return a;
}

__device__ __forceinline__ void cp16(uint32_t dst, const void* src) {
    asm volatile("cp.async.cg.shared.global [%0], [%1], 16;"
                 :: "r"(dst), "l"(src));
}
#define CP_COMMIT() asm volatile("cp.async.commit_group;" ::: "memory")
#define CP_WAIT(n)  asm volatile("cp.async.wait_group %0;" :: "n"(n) : "memory")

__device__ __forceinline__ void ldsm4(uint32_t& r0, uint32_t& r1,
                                      uint32_t& r2, uint32_t& r3, uint32_t addr) {
    asm volatile("ldmatrix.sync.aligned.m8n8.x4.shared.b16 {%0,%1,%2,%3}, [%4];"
                 : "=r"(r0), "=r"(r1), "=r"(r2), "=r"(r3) : "r"(addr));
}

__device__ __forceinline__ void mma_f16(float* c, const uint32_t* a, const uint32_t* b) {
    asm volatile("mma.sync.aligned.m16n8k16.row.col.f32.f16.f16.f32 "
                 "{%0,%1,%2,%3}, {%4,%5,%6,%7}, {%8,%9}, {%0,%1,%2,%3};"
                 : "+f"(c[0]), "+f"(c[1]), "+f"(c[2]), "+f"(c[3])
                 : "r"(a[0]), "r"(a[1]), "r"(a[2]), "r"(a[3]),
                   "r"(b[0]), "r"(b[1]));
}

__device__ __forceinline__ uint32_t packh(float x, float y) {
    __half2 p = __floats2half2_rn(x, y);
    return *(uint32_t*)&p;
}

// ---------------- fused prep kernel ------------------------------------------
#define NB_QKV  1728                        // 3 * 24 * 24
#define NB_W1   1152                        // 48 * 24
#define NB_W2   1152                        // 24 * 48
#define NB_BIAS 3
#define NB_CVT  2048
#define NB_PREP (NB_QKV + NB_W1 + NB_W2 + NB_BIAS + NB_CVT)  // 6083

__device__ __forceinline__ void tsp_tile(const float* __restrict__ W,
                                         __half* __restrict__ oh,
                                         int K, int N, int n0, int k0) {
    __shared__ float t[32][33];
    const int tx = threadIdx.x & 31, ty = threadIdx.x >> 5;
#pragma unroll
    for (int i = 0; i < 4; i++)
        t[ty + 8*i][tx] = W[(size_t)(k0 + ty + 8*i) * N + n0 + tx];
    __syncthreads();
#pragma unroll
    for (int i = 0; i < 4; i++) {
        float v = t[tx][ty + 8*i];
        oh[(size_t)(n0 + ty + 8*i) * K + k0 + tx] = __float2half_rn(v);
    }
}

__global__ void __launch_bounds__(256)
prep_all(const float* __restrict__ x1,
         const float* __restrict__ Wq, const float* __restrict__ Wk,
         const float* __restrict__ Wv,
         const float* __restrict__ W1, const float* __restrict__ W2,
         const float* __restrict__ bq, const float* __restrict__ bk,
         const float* __restrict__ bv)
{
    const int bid = blockIdx.x;
    const int tid = threadIdx.x;

    if (bid < NB_QKV) {
        const int z = bid / 576, r = bid % 576;
        const int n0 = (r % 24) * 32, k0 = (r / 24) * 32;
        const float* W = (z == 0) ? Wq : (z == 1) ? Wk : Wv;
        tsp_tile(W, g_wqkvh + (size_t)z * HID * HID, HID, HID, n0, k0);
    } else if (bid < NB_QKV + NB_W1) {
        const int r = bid - NB_QKV;
        const int n0 = (r % 48) * 32, k0 = (r / 48) * 32;   // N=FF, K=HID
        tsp_tile(W1, g_w1h, HID, FF, n0, k0);
    } else if (bid < NB_QKV + NB_W1 + NB_W2) {
        const int r = bid - (NB_QKV + NB_W1);
        const int n0 = (r % 24) * 32, k0 = (r / 24) * 32;   // N=HID, K=FF
        tsp_tile(W2, g_w2h, FF, HID, n0, k0);
    } else if (bid < NB_QKV + NB_W1 + NB_W2 + NB_BIAS) {
        const int i = (bid - (NB_QKV + NB_W1 + NB_W2)) * 256 + tid;
        if (i < HID) {
            g_bqkv[i]         = bq[i];
            g_bqkv[i + HID]   = bk[i];
            g_bqkv[i + 2*HID] = bv[i];
        }
    } else {
        const int cb = bid - (NB_QKV + NB_W1 + NB_W2 + NB_BIAS);
        const int n4 = ROWS * HID / 4;
        for (int i = cb * 256 + tid; i < n4; i += NB_CVT * 256) {
            float4 a = ((const float4*)x1)[i];
            ((__half2*)g_ah)[2*i]   = __floats2half2_rn(a.x, a.y);
            ((__half2*)g_ah)[2*i+1] = __floats2half2_rn(a.z, a.w);
        }
    }
}

// ---------------- fp16 single-pass mma.sync GEMM (128x128, 4-stage, occ 2) ---
// mode 0: fp32 out. mode 1: fp16 out. mode 2 (QKV): fp16 out, q cols scaled 1/8.
// mode 3: fp32 out with fused residual add (Cf = acc + bias + Radd[tile]).
#define ASTR    40
#define STGB    (128 * ASTR * 2)
#define STAGES  4
#define GEMM_SMEM (STAGES * 2 * STGB)        // 81920 B

__global__ void __launch_bounds__(256, 2)
gemm_mma(const __half* __restrict__ A, const __half* __restrict__ B,
         const float* __restrict__ bias,
         float* __restrict__ Cf, __half* __restrict__ Ch,
         const float* __restrict__ Radd,
         int N, int K, int relu, int mode)
{
    extern __shared__ __align__(16) char dsm[];
    __half* smA = (__half*)dsm;
    __half* smB = (__half*)(dsm + STAGES * STGB);

    const int tid  = threadIdx.x;
    const int wid  = tid >> 5, lane = tid & 31;
    const int warp_m = wid >> 2;
    const int warp_n = wid & 3;
    const int m0 = blockIdx.y << 7;
    const int n0 = blockIdx.x << 7;

    const uint32_t sA = smem_u32(smA);
    const uint32_t sB = smem_u32(smB);

    const int lrow  = tid >> 1;
    const int lcolh = (tid & 1) * 16;

    const int kb = K >> 5;

    float c[4][4][4];
#pragma unroll
    for (int i = 0; i < 4; i++)
#pragma unroll
        for (int j = 0; j < 4; j++)
#pragma unroll
            for (int r = 0; r < 4; r++) c[i][j][r] = 0.f;

    const int rowoff = ((lane >> 3) & 1) * 8 + (lane & 7);
    const int coloff = ((lane >> 4) & 1) * 8;

    auto issue = [&](int blk) {
        if (blk < kb) {
            const __half* ga = A + (size_t)(m0 + lrow) * K + blk * 32 + lcolh;
            const __half* gb = B + (size_t)(n0 + lrow) * K + blk * 32 + lcolh;
            int st = blk & (STAGES - 1);
            uint32_t da = sA + st * STGB + (lrow * ASTR + lcolh) * 2;
            uint32_t db = sB + st * STGB + (lrow * ASTR + lcolh) * 2;
            cp16(da,      ga);
            cp16(da + 16, ga + 8);
            cp16(db,      gb);
            cp16(db + 16, gb + 8);
        }
        CP_COMMIT();
    };

    issue(0); issue(1); issue(2);

    for (int blk = 0; blk < kb; blk++) {
        CP_WAIT(2);
        __syncthreads();

        const int stage = blk & (STAGES - 1);
        const uint32_t a0 = sA + stage * STGB;
        const uint32_t b0 = sB + stage * STGB;
#pragma unroll
        for (int kh = 0; kh < 2; kh++) {
            uint32_t af[4][4];
#pragma unroll
            for (int t = 0; t < 4; t++)
                ldsm4(af[t][0], af[t][1], af[t][2], af[t][3],
                      a0 + ((warp_m * 64 + t * 16 + rowoff) * ASTR + kh * 16 + coloff) * 2);
            uint32_t bf[4][2];
#pragma unroll
            for (int p = 0; p < 2; p++) {
                uint32_t r0, r1, r2, r3;
                ldsm4(r0, r1, r2, r3,
                      b0 + ((warp_n * 32 + p * 16 + rowoff) * ASTR + kh * 16 + coloff) * 2);
                bf[2*p][0]   = r0; bf[2*p][1]   = r2;
                bf[2*p+1][0] = r1; bf[2*p+1][1] = r3;
            }
#pragma unroll
            for (int i = 0; i < 4; i++)
#pragma unroll
                for (int j = 0; j < 4; j++)
                    mma_f16(c[i][j], af[i], bf[j]);
        }
        issue(blk + 3);
    }

    const float qsc = (mode == 2 && n0 < HID) ? 0.125f : 1.0f;

#pragma unroll
    for (int i = 0; i < 4; i++) {
#pragma unroll
        for (int j = 0; j < 4; j++) {
            int grow = m0 + warp_m * 64 + i * 16 + (lane >> 2);
            int gcol = n0 + warp_n * 32 + j * 8 + (lane & 3) * 2;
            float b0v = bias[gcol], b1v = bias[gcol + 1];
            float v0 = c[i][j][0] + b0v;
            float v1 = c[i][j][1] + b1v;
            float v2 = c[i][j][2] + b0v;
            float v3 = c[i][j][3] + b1v;
            if (relu) {
                v0 = fmaxf(v0, 0.f); v1 = fmaxf(v1, 0.f);
                v2 = fmaxf(v2, 0.f); v3 = fmaxf(v3, 0.f);
            }
            if (mode == 3) {
                float2 r0 = *(const float2*)(Radd + (size_t)grow * N + gcol);
                float2 r1 = *(const float2*)(Radd + (size_t)(grow + 8) * N + gcol);
                *(float2*)(Cf + (size_t)grow * N + gcol)       = make_float2(v0 + r0.x, v1 + r0.y);
                *(float2*)(Cf + (size_t)(grow + 8) * N + gcol) = make_float2(v2 + r1.x, v3 + r1.y);
            } else if (mode == 0) {
                *(float2*)(Cf + (size_t)grow * N + gcol)       = make_float2(v0, v1);
                *(float2*)(Cf + (size_t)(grow + 8) * N + gcol) = make_float2(v2, v3);
            } else {
                __half2 p0 = __floats2half2_rn(v0 * qsc, v1 * qsc);
                __half2 p1 = __floats2half2_rn(v2 * qsc, v3 * qsc);
                *(__half2*)(Ch + (size_t)grow * N + gcol)       = p0;
                *(__half2*)(Ch + (size_t)(grow + 8) * N + gcol) = p1;
            }
        }
    }
}

// ---------------- tensor-core flash attention (fp16 single-pass) -------------
#define QT 128
#define KTILE 64
#define SQ 72
#define ATTN_SMEM ((QT + 2*KTILE) * SQ * 2)    // 36864 B

__global__ void __launch_bounds__(256, 2)
attn_mma(const float* __restrict__ wm)
{
    extern __shared__ __align__(16) __half am_[];
    __half* qs = am_;                 // [row][d]
    __half* ks = qs + QT * SQ;        // [k][d]
    __half* vt = ks + KTILE * SQ;     // [d][k]

    const int tid = threadIdx.x, wid = tid >> 5, lane = tid & 31;
    const int h = blockIdx.x, b = blockIdx.z, q0 = blockIdx.y * QT;

    const uint32_t sqs = smem_u32(qs);
    const uint32_t sks = smem_u32(ks);
    const uint32_t svt = smem_u32(vt);

    // stage Q (already scaled, fp16 direct copy)
    {
        const int row = tid >> 1, cb = (tid & 1) * 32;
        const __half* src = g_qkv16 + (size_t)(b * SEQ + q0 + row) * NQKV + h * DHEAD + cb;
#pragma unroll
        for (int f = 0; f < 4; f++)
            *(uint4*)(qs + row * SQ + cb + 8 * f) = *(const uint4*)(src + 8 * f);
    }

    const int krow = tid >> 2, kcb = (tid & 3) * 16;
    uint4 rk[2], rv[2];
    {
        const __half* kp = g_qkv16 + (size_t)(b * SEQ + krow) * NQKV + HID + h * DHEAD + kcb;
        rk[0] = *(const uint4*)kp;          rk[1] = *(const uint4*)(kp + 8);
        rv[0] = *(const uint4*)(kp + HID);  rv[1] = *(const uint4*)(kp + HID + 8);
    }

    float m0 = -1e30f, m1 = -1e30f, l0 = 0.f, l1 = 0.f;
    float o[8][4];
#pragma unroll
    for (int j = 0; j < 8; j++)
#pragma unroll
        for (int r = 0; r < 4; r++) o[j][r] = 0.f;

    const int rowoff = ((lane >> 3) & 1) * 8 + (lane & 7);
    const int coloff = (lane >> 4) * 8;
    const int rA = q0 + wid * 16 + (lane >> 2);

    for (int kt = 0; kt < 16; kt++) {
        __syncthreads();
        *(uint4*)(ks + krow * SQ + kcb)     = rk[0];
        *(uint4*)(ks + krow * SQ + kcb + 8) = rk[1];
        {
            __half vv[16];
            *(uint4*)vv       = rv[0];
            *(uint4*)(vv + 8) = rv[1];
#pragma unroll
            for (int e = 0; e < 16; e++)
                vt[(kcb + e) * SQ + krow] = vv[e];
        }
        __syncthreads();
        if (kt < 15) {
            const __half* kp = g_qkv16 + (size_t)(b * SEQ + (kt + 1) * KTILE + krow) * NQKV
                               + HID + h * DHEAD + kcb;
            rk[0] = *(const uint4*)kp;          rk[1] = *(const uint4*)(kp + 8);
            rv[0] = *(const uint4*)(kp + HID);  rv[1] = *(const uint4*)(kp + HID + 8);
        }
        // mask tile (fp32, L2-resident; loads hidden under the QK MMAs)
        float2 mk0[8], mk1[8];
        {
            const float* mr0 = wm + ((size_t)b * SEQ + rA) * SEQ + kt * KTILE + (lane & 3) * 2;
            const float* mr1 = mr0 + 8 * SEQ;
#pragma unroll
            for (int j = 0; j < 8; j++) {
                mk0[j] = *(const float2*)(mr0 + 8 * j);
                mk1[j] = *(const float2*)(mr1 + 8 * j);
            }
        }

        float s[8][4];
#pragma unroll
        for (int j = 0; j < 8; j++)
#pragma unroll
            for (int r = 0; r < 4; r++) s[j][r] = 0.f;

#pragma unroll
        for (int t = 0; t < 4; t++) {
            uint32_t af[4];
            ldsm4(af[0], af[1], af[2], af[3],
                  sqs + ((wid * 16 + rowoff) * SQ + t * 16 + coloff) * 2);
#pragma unroll
            for (int p = 0; p < 4; p++) {
                uint32_t r0, r1, r2, r3;
                ldsm4(r0, r1, r2, r3,
                      sks + ((p * 16 + rowoff) * SQ + t * 16 + coloff) * 2);
                uint32_t b0[2] = {r0, r2}, b1[2] = {r1, r3};
                mma_f16(s[2*p],   af, b0);
                mma_f16(s[2*p+1], af, b1);
            }
        }

        float lm0 = -1e30f, lm1 = -1e30f;
#pragma unroll
        for (int j = 0; j < 8; j++) {
            lm0 = fmaxf(lm0, fmaxf(s[j][0], s[j][1]));
            lm1 = fmaxf(lm1, fmaxf(s[j][2], s[j][3]));
        }
        lm0 = fmaxf(lm0, __shfl_xor_sync(0xffffffffu, lm0, 1));
        lm0 = fmaxf(lm0, __shfl_xor_sync(0xffffffffu, lm0, 2));
        lm1 = fmaxf(lm1, __shfl_xor_sync(0xffffffffu, lm1, 1));
        lm1 = fmaxf(lm1, __shfl_xor_sync(0xffffffffu, lm1, 2));
        float mn0 = fmaxf(m0, lm0), mn1 = fmaxf(m1, lm1);
        float f0 = __expf(m0 - mn0), f1 = __expf(m1 - mn1);
        m0 = mn0; m1 = mn1;
        float ls0 = 0.f, ls1 = 0.f;
#pragma unroll
        for (int j = 0; j < 8; j++) {
            float e0 = __expf(s[j][0] - mn0);
            float e1 = __expf(s[j][1] - mn0);
            float e2 = __expf(s[j][2] - mn1);
            float e3 = __expf(s[j][3] - mn1);
            ls0 += e0 + e1; ls1 += e2 + e3;
            s[j][0] = e0 * mk0[j].x;
            s[j][1] = e1 * mk0[j].y;
            s[j][2] = e2 * mk1[j].x;
            s[j][3] = e3 * mk1[j].y;
        }
        ls0 += __shfl_xor_sync(0xffffffffu, ls0, 1);
        ls0 += __shfl_xor_sync(0xffffffffu, ls0, 2);
        ls1 += __shfl_xor_sync(0xffffffffu, ls1, 1);
        ls1 += __shfl_xor_sync(0xffffffffu, ls1, 2);
        l0 = l0 * f0 + ls0;
        l1 = l1 * f1 + ls1;
#pragma unroll
        for (int j = 0; j < 8; j++) {
            o[j][0] *= f0; o[j][1] *= f0;
            o[j][2] *= f1; o[j][3] *= f1;
        }

#pragma unroll
        for (int u = 0; u < 4; u++) {
            uint32_t pa[4];
            pa[0] = packh(s[2*u][0],   s[2*u][1]);
            pa[1] = packh(s[2*u][2],   s[2*u][3]);
            pa[2] = packh(s[2*u+1][0], s[2*u+1][1]);
            pa[3] = packh(s[2*u+1][2], s[2*u+1][3]);
#pragma unroll
            for (int p = 0; p < 4; p++) {
                uint32_t r0, r1, r2, r3;
                ldsm4(r0, r1, r2, r3,
                      svt + ((p * 16 + rowoff) * SQ + u * 16 + coloff) * 2);
                uint32_t b0[2] = {r0, r2}, b1[2] = {r1, r3};
                mma_f16(o[2*p],   pa, b0);
                mma_f16(o[2*p+1], pa, b1);
            }
        }
    }

    // epilogue: ctx in fp16 (halves store traffic; ln1 reads fp16)
    float inv0 = 1.0f / l0, inv1 = 1.0f / l1;
    __half* c0 = g_ctx16 + ((size_t)(b * SEQ) + rA) * HID + h * DHEAD + (lane & 3) * 2;
    __half* c1 = c0 + 8 * HID;
#pragma unroll
    for (int j = 0; j < 8; j++) {
        *(__half2*)(c0 + 8 * j) = __floats2half2_rn(o[j][0] * inv0, o[j][1] * inv0);
        *(__half2*)(c1 + 8 * j) = __floats2half2_rn(o[j][2] * inv1, o[j][3] * inv1);
    }
}

// ---------------- fused residual-add + LayerNorm (one-pass sum/sumsq) --------
// ln1: ctx fp16 + q fp16 (pre-scaled 1/8 -> rescale x8, exact pow2).
__global__ void __launch_bounds__(256)
ln1_kernel(const float* __restrict__ g, const float* __restrict__ be)
{
    const int row = blockIdx.x;
    const int tid = threadIdx.x;
    __shared__ float redS[8], redQ[8];
    __shared__ float s_mu, s_rs;

    float4 v4 = make_float4(0.f, 0.f, 0.f, 0.f);
    float ls = 0.f, lq = 0.f;
    if (tid < 192) {
        const __half2* cp = (const __half2*)(g_ctx16 + (size_t)row * HID);
        float2 c0 = __half22float2(cp[2*tid]);
        float2 c1 = __half22float2(cp[2*tid+1]);
        const __half2* qp = (const __half2*)(g_qkv16 + (size_t)row * NQKV);
        float2 q0 = __half22float2(qp[2*tid]);
        float2 q1 = __half22float2(qp[2*tid+1]);
        v4 = make_float4(c0.x + 8.f*q0.x, c0.y + 8.f*q0.y,
                         c1.x + 8.f*q1.x, c1.y + 8.f*q1.y);
        ls = v4.x + v4.y + v4.z + v4.w;
        lq = v4.x*v4.x + v4.y*v4.y + v4.z*v4.z + v4.w*v4.w;
    }
    int lane = tid & 31, wid = tid >> 5;
#pragma unroll
    for (int o = 16; o; o >>= 1) {
        ls += __shfl_xor_sync(0xffffffffu, ls, o);
        lq += __shfl_xor_sync(0xffffffffu, lq, o);
    }
    if (lane == 0) { redS[wid] = ls; redQ[wid] = lq; }
    __syncthreads();
    if (tid == 0) {
        float ts = 0.f, tq = 0.f;
#pragma unroll
        for (int i = 0; i < 8; i++) { ts += redS[i]; tq += redQ[i]; }
        float mu = ts * (1.0f / HID);
        s_mu = mu;
        s_rs = rsqrtf(tq * (1.0f / HID) - mu * mu + 1e-5f);
    }
    __syncthreads();
    float mu = s_mu, rs = s_rs;

    if (tid < 192) {
        float4 g4  = ((const float4*)g)[tid];
        float4 be4 = ((const float4*)be)[tid];
        float4 o = make_float4((v4.x - mu) * rs * g4.x + be4.x,
                               (v4.y - mu) * rs * g4.y + be4.y,
                               (v4.z - mu) * rs * g4.z + be4.z,
                               (v4.w - mu) * rs * g4.w + be4.w);
        ((float4*)(g_x + (size_t)row * HID))[tid] = o;
        ((__half2*)(g_ah + (size_t)row * HID))[2*tid]   = __floats2half2_rn(o.x, o.y);
        ((__half2*)(g_ah + (size_t)row * HID))[2*tid+1] = __floats2half2_rn(o.z, o.w);
    }
}

// ln2: g_ff2 already holds x + ff2 (residual fused into ff2 epilogue).
__global__ void __launch_bounds__(256)
ln2_kernel(const float* __restrict__ g, const float* __restrict__ be,
           float* __restrict__ out)
{
    const int row = blockIdx.x;
    const int tid = threadIdx.x;
    __shared__ float redS[8], redQ[8];
    __shared__ float s_mu, s_rs;

    float4 v4 = make_float4(0.f, 0.f, 0.f, 0.f);
    float ls = 0.f, lq = 0.f;
    if (tid < 192) {
        v4 = ((const float4*)(g_ff2 + (size_t)row * HID))[tid];
        ls = v4.x + v4.y + v4.z + v4.w;
        lq = v4.x*v4.x + v4.y*v4.y + v4.z*v4.z + v4.w*v4.w;
    }
    int lane = tid & 31, wid = tid >> 5;
#pragma unroll
    for (int o = 16; o; o >>= 1) {
        ls += __shfl_xor_sync(0xffffffffu, ls, o);
        lq += __shfl_xor_sync(0xffffffffu, lq, o);
    }
    if (lane == 0) { redS[wid] = ls; redQ[wid] = lq; }
    __syncthreads();
    if (tid == 0) {
        float ts = 0.f, tq = 0.f;
#pragma unroll
        for (int i = 0; i < 8; i++) { ts += redS[i]; tq += redQ[i]; }
        float mu = ts * (1.0f / HID);
        s_mu = mu;
        s_rs = rsqrtf(tq * (1.0f / HID) - mu * mu + 1e-5f);
    }
    __syncthreads();
    float mu = s_mu, rs = s_rs;

    if (tid < 192) {
        float4 g4  = ((const float4*)g)[tid];
        float4 be4 = ((const float4*)be)[tid];
        float4 o = make_float4((v4.x - mu) * rs * g4.x + be4.x,
                               (v4.y - mu) * rs * g4.y + be4.y,
                               (v4.z - mu) * rs * g4.z + be4.z,
                               (v4.w - mu) * rs * g4.w + be4.w);
        ((float4*)(out + (size_t)row * HID))[tid] = o;
    }
}

// ---------------- launch -----------------------------------------------------
extern "C" void kernel_launch(void* const* d_in, const int* in_sizes, int n_in,
                              void* d_out, int out_size)
{
    const float* x1  = (const float*)d_in[0];
    const float* wm  = (const float*)d_in[1];
    const float* Wq  = (const float*)d_in[2];
    const float* bq  = (const float*)d_in[3];
    const float* Wk  = (const float*)d_in[4];
    const float* bk  = (const float*)d_in[5];
    const float* Wv  = (const float*)d_in[6];
    const float* bv  = (const float*)d_in[7];
    const float* g1  = (const float*)d_in[8];
    const float* be1 = (const float*)d_in[9];
    const float* g2  = (const float*)d_in[10];
    const float* be2 = (const float*)d_in[11];
    const float* W1  = (const float*)d_in[12];
    const float* b1  = (const float*)d_in[13];
    const float* W2  = (const float*)d_in[14];
    const float* b2  = (const float*)d_in[15];
    float* out = (float*)d_out;

    void *p_ah, *p_fh, *p_w1h, *p_w2h;
    void *p_qkv16, *p_bqkv, *p_ff2, *p_wqh, *p_x;
    cudaGetSymbolAddress(&p_ah, g_ah);
    cudaGetSymbolAddress(&p_fh, g_fh);
    cudaGetSymbolAddress(&p_w1h, g_w1h);
    cudaGetSymbolAddress(&p_w2h, g_w2h);
    cudaGetSymbolAddress(&p_qkv16, g_qkv16);
    cudaGetSymbolAddress(&p_bqkv, g_bqkv);
    cudaGetSymbolAddress(&p_ff2, g_ff2);
    cudaGetSymbolAddress(&p_wqh, g_wqkvh);
    cudaGetSymbolAddress(&p_x, g_x);

    __half* ah    = (__half*)p_ah;
    __half* fh    = (__half*)p_fh;
    __half* wqh   = (__half*)p_wqh;
    __half* w1h   = (__half*)p_w1h;
    __half* w2h   = (__half*)p_w2h;
    __half* qkv16 = (__half*)p_qkv16;
    float* bqkv   = (float*)p_bqkv;
    float* ff2    = (float*)p_ff2;
    float* xbuf   = (float*)p_x;

    cudaFuncSetAttribute(attn_mma,
                         cudaFuncAttributeMaxDynamicSharedMemorySize, ATTN_SMEM);
    cudaFuncSetAttribute(gemm_mma,
                         cudaFuncAttributeMaxDynamicSharedMemorySize, GEMM_SMEM);

    // 1: fused prep (weight transposes + bias + x1 convert) in ONE launch
    prep_all<<<NB_PREP, 256>>>(x1, Wq, Wk, Wv, W1, W2, bq, bk, bv);

    // 2: fused QKV GEMM: fp16 out, q pre-scaled 1/8 (mode 2)
    gemm_mma<<<dim3(NQKV/128, ROWS/128), 256, GEMM_SMEM>>>(
        ah, wqh, bqkv, nullptr, qkv16, nullptr, NQKV, HID, 0, 2);

    // 3: fp16 flash attention; ctx stored fp16
    attn_mma<<<dim3(NHEAD, SEQ/QT, BATCH), 256, ATTN_SMEM>>>(wm);

    // 4: x = LN(ctx + q_mixed), one-pass reduction, fused fp16 emit
    ln1_kernel<<<ROWS, 256>>>(g1, be1);

    // 5: ff1 = relu(x @ W1 + b1) -> fp16
    gemm_mma<<<dim3(FF/128, ROWS/128), 256, GEMM_SMEM>>>(
        ah, w1h, b1, nullptr, fh, nullptr, FF, HID, 1, 1);

    // 6: ff2 = ff1 @ W2 + b2 + x  (residual fused into epilogue, mode 3)
    gemm_mma<<<dim3(HID/128, ROWS/128), 256, GEMM_SMEM>>>(
        fh, w2h, b2, ff2, nullptr, xbuf, HID, FF, 0, 3);

    // 7: out = LN(g_ff2)   (already contains x + ff2)
    ln2_kernel<<<ROWS, 256>>>(g2, be2, out);
}